// round 4
// baseline (speedup 1.0000x reference)
#include <cuda_runtime.h>
#include <cuda_bf16.h>
#include <cstdint>

#define NV   40968           // total vertices (B*V)
#define VPER 10242
#define XSTR 392             // padded row stride of X0 (387 used)
#define PTOT 2132480         // total floats in P tables

// P table offsets (floats) per feature map: B*HW*128 cumulative
#define POFF0 0
#define POFF1 1605632
#define POFF2 2007040
#define POFF3 2107392

// ---------------- device scratch (module globals; no allocations) --------
__device__ float g_P[PTOT];
__device__ float g_X0[(size_t)NV * XSTR];
__device__ float g_bufA[(size_t)NV * 128];
__device__ float g_bufB[(size_t)NV * 128];
__device__ float g_H1[(size_t)NV * 128];
__device__ int   g_cnt[NV];
__device__ int   g_offs[NV + 1];
__device__ int   g_entries[245760];

// =========================================================================
// zero the degree-count buffer
// =========================================================================
__global__ void zero_cnt_kernel()
{
    int i = blockIdx.x * blockDim.x + threadIdx.x;
    if (i < NV) g_cnt[i] = 0;
}

// =========================================================================
// Kernel 1: per-pixel projection P_m[b,pix,:] = fm[b,:,pix] @ Wslice_m
// Each block handles 64 pixels x 128 outputs, loops full channel dim.
// 128 threads, 8x8 micro-tile, plain FFMA.
// =========================================================================
__global__ void __launch_bounds__(128) precompute_kernel(
    const float* __restrict__ f1, const float* __restrict__ f2,
    const float* __restrict__ f3, const float* __restrict__ f4,
    const float* __restrict__ BW)
{
    __shared__ float As[32][68];
    __shared__ float Bs[32][128];

    int bid = blockIdx.x;
    int m, local;
    if (bid < 196)      { m = 0; local = bid; }          // 49 mtiles * 4 b
    else if (bid < 248) { m = 1; local = bid - 196; }    // 13 mtiles * 4 b
    else if (bid < 264) { m = 2; local = bid - 248; }    // 4 mtiles * 4 b
    else                { m = 3; local = bid - 264; }    // 1 mtile  * 4 b

    int b  = local & 3;
    int mt = local >> 2;

    const float* fm;
    int HW, C, WO; size_t poff;
    if (m == 0)      { fm = f1; HW = 3136; C = 256;  WO = 0;    poff = POFF0; }
    else if (m == 1) { fm = f2; HW = 784;  C = 512;  WO = 256;  poff = POFF1; }
    else if (m == 2) { fm = f3; HW = 196;  C = 1024; WO = 768;  poff = POFF2; }
    else             { fm = f4; HW = 49;   C = 2048; WO = 1792; poff = POFF3; }

    int p0 = mt * 64;
    int tid = threadIdx.x;
    int rowg = tid & 7;          // 0..7
    int colg = tid >> 3;         // 0..15
    int r0 = rowg * 8;
    int c0 = colg * 8;

    float acc[8][8];
#pragma unroll
    for (int i = 0; i < 8; i++)
#pragma unroll
        for (int j = 0; j < 8; j++) acc[i][j] = 0.f;

    int nchunk = C >> 5;
    for (int ch = 0; ch < nchunk; ch++) {
        int kk = ch * 32;
        // A tile: 64 pixels x 32 channels (coalesced along pixels)
#pragma unroll
        for (int i = 0; i < 16; i++) {
            int lin = tid + i * 128;
            int c = lin >> 6;
            int p = lin & 63;
            float v = 0.f;
            if (p0 + p < HW)
                v = fm[((size_t)b * C + (kk + c)) * HW + p0 + p];
            As[c][p] = v;
        }
        // B tile: 32 x 128 weights
#pragma unroll
        for (int i = 0; i < 8; i++) {
            int lin4 = tid + i * 128;
            int k = lin4 >> 5;
            int n4 = (lin4 & 31) * 4;
            float4 v = *(const float4*)&BW[(size_t)(WO + kk + k) * 128 + n4];
            *(float4*)&Bs[k][n4] = v;
        }
        __syncthreads();
#pragma unroll 4
        for (int k = 0; k < 32; k++) {
            float4 aA = *(const float4*)&As[k][r0];
            float4 aB = *(const float4*)&As[k][r0 + 4];
            float4 bA = *(const float4*)&Bs[k][c0];
            float4 bB = *(const float4*)&Bs[k][c0 + 4];
            float a[8] = {aA.x, aA.y, aA.z, aA.w, aB.x, aB.y, aB.z, aB.w};
            float bb[8] = {bA.x, bA.y, bA.z, bA.w, bB.x, bB.y, bB.z, bB.w};
#pragma unroll
            for (int i = 0; i < 8; i++)
#pragma unroll
                for (int j = 0; j < 8; j++) acc[i][j] += a[i] * bb[j];
        }
        __syncthreads();
    }
    // epilogue: direct store into P
    size_t pbase = poff + (size_t)b * HW * 128;
#pragma unroll
    for (int i = 0; i < 8; i++) {
        int pix = p0 + r0 + i;
        if (pix >= HW) continue;
        float* dst = &g_P[pbase + (size_t)pix * 128 + c0];
#pragma unroll
        for (int j = 0; j < 8; j += 4) {
            float4 o = make_float4(acc[i][j], acc[i][j+1], acc[i][j+2], acc[i][j+3]);
            *(float4*)&dst[j] = o;
        }
    }
}

// =========================================================================
// Kernel 2: bilinear sampler + bias + relu + assemble X0 row
// one warp per vertex; lane owns 4 channels
// =========================================================================
__global__ void sampler_kernel(
    const float* __restrict__ av, const float* __restrict__ vp,
    const float* __restrict__ enc, const float* __restrict__ bias)
{
    int gwarp = (blockIdx.x * blockDim.x + threadIdx.x) >> 5;
    int lane = threadIdx.x & 31;
    if (gwarp >= NV) return;
    int v = gwarp;
    int b = v / VPER;

    float gx = av[(size_t)v * 3 + 0];
    float gy = av[(size_t)v * 3 + 1];

    float4 acc = make_float4(0.f, 0.f, 0.f, 0.f);
#pragma unroll
    for (int m = 0; m < 4; m++) {
        const int DIMm = (m == 0) ? 56 : (m == 1) ? 28 : (m == 2) ? 14 : 7;
        const int HWm  = DIMm * DIMm;
        const size_t POm = (m == 0) ? POFF0 : (m == 1) ? POFF1 : (m == 2) ? POFF2 : POFF3;
        int w = DIMm;
        float fx = (gx + 1.f) * 0.5f * (float)(w - 1);
        float fy = (gy + 1.f) * 0.5f * (float)(w - 1);
        float x0f = floorf(fx), y0f = floorf(fy);
        float wx1 = fx - x0f, wy1 = fy - y0f;
        float wx0 = 1.f - wx1, wy0 = 1.f - wy1;
        int x0 = min(max((int)x0f, 0), w - 1);
        int x1 = min(max((int)x0f + 1, 0), w - 1);
        int y0 = min(max((int)y0f, 0), w - 1);
        int y1 = min(max((int)y0f + 1, 0), w - 1);
        size_t base = POm + (size_t)b * HWm * 128;
        float4 c00 = ((const float4*)&g_P[base + (size_t)(y0 * w + x0) * 128])[lane];
        float4 c01 = ((const float4*)&g_P[base + (size_t)(y0 * w + x1) * 128])[lane];
        float4 c10 = ((const float4*)&g_P[base + (size_t)(y1 * w + x0) * 128])[lane];
        float4 c11 = ((const float4*)&g_P[base + (size_t)(y1 * w + x1) * 128])[lane];
        float w00 = wy0 * wx0, w01 = wy0 * wx1, w10 = wy1 * wx0, w11 = wy1 * wx1;
        acc.x += w00 * c00.x + w01 * c01.x + w10 * c10.x + w11 * c11.x;
        acc.y += w00 * c00.y + w01 * c01.y + w10 * c10.y + w11 * c11.y;
        acc.z += w00 * c00.z + w01 * c01.z + w10 * c10.z + w11 * c11.z;
        acc.w += w00 * c00.w + w01 * c01.w + w10 * c10.w + w11 * c11.w;
    }
    float4 bb = ((const float4*)bias)[lane];
    acc.x = fmaxf(acc.x + bb.x, 0.f);
    acc.y = fmaxf(acc.y + bb.y, 0.f);
    acc.z = fmaxf(acc.z + bb.z, 0.f);
    acc.w = fmaxf(acc.w + bb.w, 0.f);
    float* row = &g_X0[(size_t)v * XSTR];
    ((float4*)row)[lane] = acc;
    if (lane < 3) row[128 + lane] = vp[(size_t)v * 3 + lane];
#pragma unroll
    for (int j = 0; j < 8; j++)
        row[131 + lane * 8 + j] = enc[(size_t)b * 256 + lane * 8 + j];
}

// =========================================================================
// CSR build  (edges are INT32: jax x64 is disabled, astype(int64) is a no-op)
// =========================================================================
__global__ void hist_kernel(const int* __restrict__ edges, int E)
{
    int i = blockIdx.x * blockDim.x + threadIdx.x;
    if (i >= E) return;
    int v0 = edges[2 * i];
    int v1 = edges[2 * i + 1];
    atomicAdd(&g_cnt[v0], 1);
    atomicAdd(&g_cnt[v1], 1);
}

__global__ void scan_kernel()
{
    __shared__ int part[1024];
    const int n = NV;
    int t = threadIdx.x;
    int chunk = (n + 1023) >> 10;
    int base = t * chunk;
    int sum = 0;
    for (int j = 0; j < chunk; j++) {
        int idx = base + j;
        if (idx < n) sum += g_cnt[idx];
    }
    part[t] = sum;
    __syncthreads();
    for (int off = 1; off < 1024; off <<= 1) {
        int v = 0;
        if (t >= off) v = part[t - off];
        __syncthreads();
        part[t] += v;
        __syncthreads();
    }
    int run = part[t] - sum;  // exclusive prefix at chunk start
    for (int j = 0; j < chunk; j++) {
        int idx = base + j;
        if (idx < n) { g_offs[idx] = run; run += g_cnt[idx]; }
    }
    if (t == 1023) g_offs[n] = part[1023];
}

__global__ void fill_kernel(const int* __restrict__ edges, int E)
{
    int i = blockIdx.x * blockDim.x + threadIdx.x;
    if (i >= E) return;
    int v0 = edges[2 * i];
    int v1 = edges[2 * i + 1];
    int p0 = atomicAdd(&g_cnt[v0], 1);
    g_entries[g_offs[v0] + p0] = v1;
    int p1 = atomicAdd(&g_cnt[v1], 1);
    g_entries[g_offs[v1] + p1] = v0;
}

// =========================================================================
// Dual GEMM: H0 = act(X) @ W0 + b0 ; g_H1 = act(X) @ W1 + b1
// BM=64, BN=256 (128 per W), BK=32, 128 threads, 8x16 micro, plain FFMA.
// xsel: 0 -> g_X0 (ld XSTR), 1 -> g_bufA, 2 -> g_bufB (ld 128)
// osel: 1 -> H0 = g_bufA, 2 -> H0 = g_bufB
// =========================================================================
__global__ void __launch_bounds__(128, 2) gemm_dual_kernel(
    int xsel, int Kin, int reluIn,
    const float* __restrict__ W0, const float* __restrict__ b0,
    const float* __restrict__ W1, const float* __restrict__ b1,
    int osel)
{
    __shared__ float As[32][68];
    __shared__ float Bs[32][256];

    const float* X = (xsel == 0) ? g_X0 : (xsel == 1) ? g_bufA : g_bufB;
    int ldx = (xsel == 0) ? XSTR : 128;
    float* H0 = (osel == 1) ? g_bufA : g_bufB;

    int tid = threadIdx.x;
    int row0 = blockIdx.x * 64;
    int rowg = tid & 7;          // 0..7
    int colg = tid >> 3;         // 0..15
    int r0 = rowg * 8;
    int c0 = colg * 16;

    float acc[8][16];
#pragma unroll
    for (int i = 0; i < 8; i++)
#pragma unroll
        for (int j = 0; j < 16; j++) acc[i][j] = 0.f;

    for (int kc = 0; kc < Kin; kc += 32) {
        int kmax = min(32, Kin - kc);
        // ---- A tile (64 rows x 32 cols), optional relu on load ----
#pragma unroll
        for (int i = 0; i < 4; i++) {
            int f4 = tid + i * 128;         // 0..511
            int r = f4 >> 3;
            int q = (f4 & 7) * 4;
            float4 v = make_float4(0.f, 0.f, 0.f, 0.f);
            int grow = row0 + r;
            if (grow < NV) {
                if (q + 3 < kmax) {
                    v = *(const float4*)&X[(size_t)grow * ldx + kc + q];
                } else {
                    float t0 = (q + 0 < kmax) ? X[(size_t)grow * ldx + kc + q + 0] : 0.f;
                    float t1 = (q + 1 < kmax) ? X[(size_t)grow * ldx + kc + q + 1] : 0.f;
                    float t2 = (q + 2 < kmax) ? X[(size_t)grow * ldx + kc + q + 2] : 0.f;
                    float t3 = (q + 3 < kmax) ? X[(size_t)grow * ldx + kc + q + 3] : 0.f;
                    v = make_float4(t0, t1, t2, t3);
                }
            }
            if (reluIn) {
                v.x = fmaxf(v.x, 0.f); v.y = fmaxf(v.y, 0.f);
                v.z = fmaxf(v.z, 0.f); v.w = fmaxf(v.w, 0.f);
            }
            As[q + 0][r] = v.x; As[q + 1][r] = v.y;
            As[q + 2][r] = v.z; As[q + 3][r] = v.w;
        }
        // ---- B tile (32 x 256 = W0 chunk | W1 chunk) ----
#pragma unroll
        for (int i = 0; i < 16; i++) {
            int f4 = tid + i * 128;         // 0..2047
            int k = f4 >> 6;
            int n4 = (f4 & 63) * 4;
            float4 v = make_float4(0.f, 0.f, 0.f, 0.f);
            if (k < kmax) {
                const float* Wp = (n4 < 128) ? W0 : W1;
                int nn = n4 & 127;
                v = *(const float4*)&Wp[(size_t)(kc + k) * 128 + nn];
            }
            *(float4*)&Bs[k][n4] = v;
        }
        __syncthreads();
#pragma unroll 2
        for (int k = 0; k < 32; k++) {
            float4 aA = *(const float4*)&As[k][r0];
            float4 aB = *(const float4*)&As[k][r0 + 4];
            float4 b0v = *(const float4*)&Bs[k][c0];
            float4 b1v = *(const float4*)&Bs[k][c0 + 4];
            float4 b2v = *(const float4*)&Bs[k][c0 + 8];
            float4 b3v = *(const float4*)&Bs[k][c0 + 12];
            float a[8]  = {aA.x, aA.y, aA.z, aA.w, aB.x, aB.y, aB.z, aB.w};
            float bb[16] = {b0v.x, b0v.y, b0v.z, b0v.w, b1v.x, b1v.y, b1v.z, b1v.w,
                            b2v.x, b2v.y, b2v.z, b2v.w, b3v.x, b3v.y, b3v.z, b3v.w};
#pragma unroll
            for (int i = 0; i < 8; i++)
#pragma unroll
                for (int j = 0; j < 16; j++) acc[i][j] += a[i] * bb[j];
        }
        __syncthreads();
    }
    // ---- epilogue ----
    const float* bias;
    float* Hout;
    int cbase;
    if (colg < 8) { Hout = H0;   bias = b0; cbase = colg * 16; }
    else          { Hout = g_H1; bias = b1; cbase = (colg - 8) * 16; }
    float4 bv[4];
#pragma unroll
    for (int q = 0; q < 4; q++) bv[q] = *(const float4*)&bias[cbase + q * 4];
#pragma unroll
    for (int i = 0; i < 8; i++) {
        int grow = row0 + r0 + i;
        if (grow >= NV) continue;
        float* dst = &Hout[(size_t)grow * 128 + cbase];
#pragma unroll
        for (int q = 0; q < 4; q++) {
            float4 o = make_float4(acc[i][q * 4 + 0] + bv[q].x,
                                   acc[i][q * 4 + 1] + bv[q].y,
                                   acc[i][q * 4 + 2] + bv[q].z,
                                   acc[i][q * 4 + 3] + bv[q].w);
            *(float4*)&dst[q * 4] = o;
        }
    }
}

// =========================================================================
// Gather: OUT[v] (holding h0) += sum_{nb in adj(v)} g_H1[nb]
// osel: 1 -> g_bufA, 2 -> g_bufB
// =========================================================================
__global__ void gather_kernel(int osel)
{
    float* OUT = (osel == 1) ? g_bufA : g_bufB;
    int gwarp = (blockIdx.x * blockDim.x + threadIdx.x) >> 5;
    int lane = threadIdx.x & 31;
    if (gwarp >= NV) return;
    int v = gwarp;
    int s = g_offs[v], e = g_offs[v + 1];
    float4 acc = ((const float4*)&OUT[(size_t)v * 128])[lane];
    for (int i = s; i < e; i++) {
        int nb = g_entries[i];
        float4 h = ((const float4*)&g_H1[(size_t)nb * 128])[lane];
        acc.x += h.x; acc.y += h.y; acc.z += h.z; acc.w += h.w;
    }
    ((float4*)&OUT[(size_t)v * 128])[lane] = acc;
}

// =========================================================================
// Final projection: out = relu(X) @ off_w + off_b   (128 -> 3)
// =========================================================================
__global__ void final_kernel(int xsel,
                             const float* __restrict__ ow, const float* __restrict__ ob,
                             float* __restrict__ out)
{
    const float* X = (xsel == 1) ? g_bufA : g_bufB;
    int gwarp = (blockIdx.x * blockDim.x + threadIdx.x) >> 5;
    int lane = threadIdx.x & 31;
    if (gwarp >= NV) return;
    int v = gwarp;
    float4 x = ((const float4*)&X[(size_t)v * 128])[lane];
    x.x = fmaxf(x.x, 0.f); x.y = fmaxf(x.y, 0.f);
    x.z = fmaxf(x.z, 0.f); x.w = fmaxf(x.w, 0.f);
    const float* wr = &ow[(size_t)(lane * 4) * 3];
    float s0 = x.x * wr[0] + x.y * wr[3] + x.z * wr[6] + x.w * wr[9];
    float s1 = x.x * wr[1] + x.y * wr[4] + x.z * wr[7] + x.w * wr[10];
    float s2 = x.x * wr[2] + x.y * wr[5] + x.z * wr[8] + x.w * wr[11];
#pragma unroll
    for (int o = 16; o > 0; o >>= 1) {
        s0 += __shfl_down_sync(0xffffffffu, s0, o);
        s1 += __shfl_down_sync(0xffffffffu, s1, o);
        s2 += __shfl_down_sync(0xffffffffu, s2, o);
    }
    if (lane == 0) {
        out[(size_t)v * 3 + 0] = s0 + ob[0];
        out[(size_t)v * 3 + 1] = s1 + ob[1];
        out[(size_t)v * 3 + 2] = s2 + ob[2];
    }
}

// =========================================================================
extern "C" void kernel_launch(void* const* d_in, const int* in_sizes, int n_in,
                              void* d_out, int out_size)
{
    const float* f1   = (const float*)d_in[0];
    const float* f2   = (const float*)d_in[1];
    const float* f3   = (const float*)d_in[2];
    const float* f4   = (const float*)d_in[3];
    const float* av   = (const float*)d_in[4];
    const float* vp   = (const float*)d_in[5];
    const float* enc  = (const float*)d_in[6];
    const int*   edges = (const int*)d_in[7];     // int32 on device (jax x64 off)
    const float* bw   = (const float*)d_in[8];
    const float* bb   = (const float*)d_in[9];
    const float* g0w0 = (const float*)d_in[10];
    const float* g0b0 = (const float*)d_in[11];
    const float* g0w1 = (const float*)d_in[12];
    const float* g0b1 = (const float*)d_in[13];
    const float* gw0  = (const float*)d_in[14];
    const float* gb0  = (const float*)d_in[15];
    const float* gw1  = (const float*)d_in[16];
    const float* gb1  = (const float*)d_in[17];
    const float* ow   = (const float*)d_in[18];
    const float* ob   = (const float*)d_in[19];
    float* out = (float*)d_out;

    int E = in_sizes[7] / 2;   // element count / 2 ints per edge

    const int WARP_GRID = (NV + 7) / 8;   // 8 warps (vertices) per 256-thread block

    // P projection tables (direct store, no zeroing needed)
    precompute_kernel<<<268, 128>>>(f1, f2, f3, f4, bw);
    sampler_kernel<<<WARP_GRID, 256>>>(av, vp, enc, bb);

    // CSR build
    zero_cnt_kernel<<<(NV + 255) / 256, 256>>>();
    hist_kernel<<<(E + 255) / 256, 256>>>(edges, E);
    scan_kernel<<<1, 1024>>>();
    zero_cnt_kernel<<<(NV + 255) / 256, 256>>>();
    fill_kernel<<<(E + 255) / 256, 256>>>(edges, E);

    const int GEMM_GRID = (NV + 63) / 64;   // 641

    // layer 0 (Kin = 387, no relu on input), H0 -> bufA
    gemm_dual_kernel<<<GEMM_GRID, 128>>>(0, 387, 0, g0w0, g0b0, g0w1, g0b1, 1);
    gather_kernel<<<WARP_GRID, 256>>>(1);

    // layers 1..7 (Kin = 128, relu on input), ping-pong bufA <-> bufB
    int cur = 1, nxt = 2;
    for (int i = 0; i < 7; i++) {
        gemm_dual_kernel<<<GEMM_GRID, 128>>>(cur, 128, 1,
                                             gw0 + (size_t)i * 16384, gb0 + (size_t)i * 128,
                                             gw1 + (size_t)i * 16384, gb1 + (size_t)i * 128,
                                             nxt);
        gather_kernel<<<WARP_GRID, 256>>>(nxt);
        int t = cur; cur = nxt; nxt = t;
    }

    final_kernel<<<WARP_GRID, 256>>>(cur, ow, ob, out);
}

// round 5
// speedup vs baseline: 1.0090x; 1.0090x over previous
#include <cuda_runtime.h>
#include <cuda_bf16.h>
#include <cstdint>

#define NV   40968           // total vertices (B*V)
#define VPER 10242
#define XSTR 392             // padded row stride of X0 (387 used)
#define PTOT 2132480         // total floats in P tables

// P table offsets (floats) per feature map: B*HW*128 cumulative
#define POFF0 0
#define POFF1 1605632
#define POFF2 2007040
#define POFF3 2107392

// ---------------- device scratch (module globals; no allocations) --------
__device__ float g_P[PTOT];
__device__ float g_X0[(size_t)NV * XSTR];
__device__ float g_bufA[(size_t)NV * 128];
__device__ float g_bufB[(size_t)NV * 128];
__device__ float g_H1[(size_t)NV * 128];
__device__ int   g_cnt[NV];
__device__ int   g_offs[NV + 1];
__device__ int   g_entries[245760];

// ---------------- f32x2 helpers ----------------
__device__ __forceinline__ unsigned long long dup2(float x) {
    unsigned long long r;
    asm("mov.b64 %0, {%1, %1};" : "=l"(r) : "f"(x));
    return r;
}
__device__ __forceinline__ void ffma2(unsigned long long &d, unsigned long long a, unsigned long long b) {
    asm("fma.rn.f32x2 %0, %1, %2, %0;" : "+l"(d) : "l"(a), "l"(b));
}
__device__ __forceinline__ float2 unpk(unsigned long long v) {
    float2 r;
    asm("mov.b64 {%0, %1}, %2;" : "=f"(r.x), "=f"(r.y) : "l"(v));
    return r;
}

// =========================================================================
// zero the degree-count buffer
// =========================================================================
__global__ void zero_cnt_kernel()
{
    int i = blockIdx.x * blockDim.x + threadIdx.x;
    if (i < NV) g_cnt[i] = 0;
}

// =========================================================================
// Kernel 1: per-pixel projection P_m[b,pix,:] = fm[b,:,pix] @ Wslice_m
// 64 pixels x 128 outputs per block, full channel loop, f32x2 FFMA.
// =========================================================================
__global__ void __launch_bounds__(128) precompute_kernel(
    const float* __restrict__ f1, const float* __restrict__ f2,
    const float* __restrict__ f3, const float* __restrict__ f4,
    const float* __restrict__ BW)
{
    __shared__ float As[32][68];
    __shared__ float Bs[32][128];

    int bid = blockIdx.x;
    int m, local;
    if (bid < 196)      { m = 0; local = bid; }          // 49 mtiles * 4 b
    else if (bid < 248) { m = 1; local = bid - 196; }    // 13 mtiles * 4 b
    else if (bid < 264) { m = 2; local = bid - 248; }    // 4 mtiles * 4 b
    else                { m = 3; local = bid - 264; }    // 1 mtile  * 4 b

    int b  = local & 3;
    int mt = local >> 2;

    const float* fm;
    int HW, C, WO; size_t poff;
    if (m == 0)      { fm = f1; HW = 3136; C = 256;  WO = 0;    poff = POFF0; }
    else if (m == 1) { fm = f2; HW = 784;  C = 512;  WO = 256;  poff = POFF1; }
    else if (m == 2) { fm = f3; HW = 196;  C = 1024; WO = 768;  poff = POFF2; }
    else             { fm = f4; HW = 49;   C = 2048; WO = 1792; poff = POFF3; }

    int p0 = mt * 64;
    int tid = threadIdx.x;
    int rowg = tid & 7;          // 0..7
    int colg = tid >> 3;         // 0..15
    int r0 = rowg * 8;
    int c0 = colg * 8;

    unsigned long long acc[8][4];
#pragma unroll
    for (int i = 0; i < 8; i++)
#pragma unroll
        for (int j = 0; j < 4; j++) acc[i][j] = 0ULL;

    int nchunk = C >> 5;
    for (int ch = 0; ch < nchunk; ch++) {
        int kk = ch * 32;
        // A tile: 64 pixels x 32 channels (coalesced along pixels)
#pragma unroll
        for (int i = 0; i < 16; i++) {
            int lin = tid + i * 128;
            int c = lin >> 6;
            int p = lin & 63;
            float v = 0.f;
            if (p0 + p < HW)
                v = fm[((size_t)b * C + (kk + c)) * HW + p0 + p];
            As[c][p] = v;
        }
        // B tile: 32 x 128 weights
#pragma unroll
        for (int i = 0; i < 8; i++) {
            int lin4 = tid + i * 128;
            int k = lin4 >> 5;
            int n4 = (lin4 & 31) * 4;
            float4 v = *(const float4*)&BW[(size_t)(WO + kk + k) * 128 + n4];
            *(float4*)&Bs[k][n4] = v;
        }
        __syncthreads();
#pragma unroll 2
        for (int k = 0; k < 32; k++) {
            float4 aA = *(const float4*)&As[k][r0];
            float4 aB = *(const float4*)&As[k][r0 + 4];
            unsigned long long ad[8] = {dup2(aA.x), dup2(aA.y), dup2(aA.z), dup2(aA.w),
                                        dup2(aB.x), dup2(aB.y), dup2(aB.z), dup2(aB.w)};
            ulonglong2 bp0 = *(const ulonglong2*)&Bs[k][c0];
            ulonglong2 bp1 = *(const ulonglong2*)&Bs[k][c0 + 4];
            unsigned long long bb[4] = {bp0.x, bp0.y, bp1.x, bp1.y};
#pragma unroll
            for (int i = 0; i < 8; i++)
#pragma unroll
                for (int j = 0; j < 4; j++) ffma2(acc[i][j], ad[i], bb[j]);
        }
        __syncthreads();
    }
    // epilogue: direct store into P
    size_t pbase = poff + (size_t)b * HW * 128;
#pragma unroll
    for (int i = 0; i < 8; i++) {
        int pix = p0 + r0 + i;
        if (pix >= HW) continue;
        float* dst = &g_P[pbase + (size_t)pix * 128 + c0];
#pragma unroll
        for (int j = 0; j < 2; j++) {
            float2 vA = unpk(acc[i][j * 2]);
            float2 vB = unpk(acc[i][j * 2 + 1]);
            float4 o = make_float4(vA.x, vA.y, vB.x, vB.y);
            *(float4*)&dst[j * 4] = o;
        }
    }
}

// =========================================================================
// Kernel 2: bilinear sampler + bias + relu + assemble X0 row
// one warp per vertex; lane owns 4 channels
// =========================================================================
__global__ void sampler_kernel(
    const float* __restrict__ av, const float* __restrict__ vp,
    const float* __restrict__ enc, const float* __restrict__ bias)
{
    int gwarp = (blockIdx.x * blockDim.x + threadIdx.x) >> 5;
    int lane = threadIdx.x & 31;
    if (gwarp >= NV) return;
    int v = gwarp;
    int b = v / VPER;

    float gx = av[(size_t)v * 3 + 0];
    float gy = av[(size_t)v * 3 + 1];

    float4 acc = make_float4(0.f, 0.f, 0.f, 0.f);
#pragma unroll
    for (int m = 0; m < 4; m++) {
        const int DIMm = (m == 0) ? 56 : (m == 1) ? 28 : (m == 2) ? 14 : 7;
        const int HWm  = DIMm * DIMm;
        const size_t POm = (m == 0) ? POFF0 : (m == 1) ? POFF1 : (m == 2) ? POFF2 : POFF3;
        int w = DIMm;
        float fx = (gx + 1.f) * 0.5f * (float)(w - 1);
        float fy = (gy + 1.f) * 0.5f * (float)(w - 1);
        float x0f = floorf(fx), y0f = floorf(fy);
        float wx1 = fx - x0f, wy1 = fy - y0f;
        float wx0 = 1.f - wx1, wy0 = 1.f - wy1;
        int x0 = min(max((int)x0f, 0), w - 1);
        int x1 = min(max((int)x0f + 1, 0), w - 1);
        int y0 = min(max((int)y0f, 0), w - 1);
        int y1 = min(max((int)y0f + 1, 0), w - 1);
        size_t base = POm + (size_t)b * HWm * 128;
        float4 c00 = ((const float4*)&g_P[base + (size_t)(y0 * w + x0) * 128])[lane];
        float4 c01 = ((const float4*)&g_P[base + (size_t)(y0 * w + x1) * 128])[lane];
        float4 c10 = ((const float4*)&g_P[base + (size_t)(y1 * w + x0) * 128])[lane];
        float4 c11 = ((const float4*)&g_P[base + (size_t)(y1 * w + x1) * 128])[lane];
        float w00 = wy0 * wx0, w01 = wy0 * wx1, w10 = wy1 * wx0, w11 = wy1 * wx1;
        acc.x += w00 * c00.x + w01 * c01.x + w10 * c10.x + w11 * c11.x;
        acc.y += w00 * c00.y + w01 * c01.y + w10 * c10.y + w11 * c11.y;
        acc.z += w00 * c00.z + w01 * c01.z + w10 * c10.z + w11 * c11.z;
        acc.w += w00 * c00.w + w01 * c01.w + w10 * c10.w + w11 * c11.w;
    }
    float4 bb = ((const float4*)bias)[lane];
    acc.x = fmaxf(acc.x + bb.x, 0.f);
    acc.y = fmaxf(acc.y + bb.y, 0.f);
    acc.z = fmaxf(acc.z + bb.z, 0.f);
    acc.w = fmaxf(acc.w + bb.w, 0.f);
    float* row = &g_X0[(size_t)v * XSTR];
    ((float4*)row)[lane] = acc;
    if (lane < 3) row[128 + lane] = vp[(size_t)v * 3 + lane];
#pragma unroll
    for (int j = 0; j < 8; j++)
        row[131 + lane * 8 + j] = enc[(size_t)b * 256 + lane * 8 + j];
}

// =========================================================================
// CSR build  (edges are INT32 on device)
// =========================================================================
__global__ void hist_kernel(const int* __restrict__ edges, int E)
{
    int i = blockIdx.x * blockDim.x + threadIdx.x;
    if (i >= E) return;
    int v0 = edges[2 * i];
    int v1 = edges[2 * i + 1];
    atomicAdd(&g_cnt[v0], 1);
    atomicAdd(&g_cnt[v1], 1);
}

__global__ void scan_kernel()
{
    __shared__ int part[1024];
    const int n = NV;
    int t = threadIdx.x;
    int chunk = (n + 1023) >> 10;
    int base = t * chunk;
    int sum = 0;
    for (int j = 0; j < chunk; j++) {
        int idx = base + j;
        if (idx < n) sum += g_cnt[idx];
    }
    part[t] = sum;
    __syncthreads();
    for (int off = 1; off < 1024; off <<= 1) {
        int v = 0;
        if (t >= off) v = part[t - off];
        __syncthreads();
        part[t] += v;
        __syncthreads();
    }
    int run = part[t] - sum;  // exclusive prefix at chunk start
    for (int j = 0; j < chunk; j++) {
        int idx = base + j;
        if (idx < n) { g_offs[idx] = run; run += g_cnt[idx]; }
    }
    if (t == 1023) g_offs[n] = part[1023];
}

__global__ void fill_kernel(const int* __restrict__ edges, int E)
{
    int i = blockIdx.x * blockDim.x + threadIdx.x;
    if (i >= E) return;
    int v0 = edges[2 * i];
    int v1 = edges[2 * i + 1];
    int p0 = atomicAdd(&g_cnt[v0], 1);
    g_entries[g_offs[v0] + p0] = v1;
    int p1 = atomicAdd(&g_cnt[v1], 1);
    g_entries[g_offs[v1] + p1] = v0;
}

// =========================================================================
// Dual GEMM: H0 = act(X) @ W0 + b0 ; g_H1 = act(X) @ W1 + b1
// BM=64, BN=256 (128 per W), BK=32, 128 threads, 8x16 micro (f32x2).
// xsel: 0 -> g_X0 (ld XSTR), 1 -> g_bufA, 2 -> g_bufB (ld 128)
// osel: 1 -> H0 = g_bufA, 2 -> H0 = g_bufB
// =========================================================================
__global__ void __launch_bounds__(128, 2) gemm_dual_kernel(
    int xsel, int Kin, int reluIn,
    const float* __restrict__ W0, const float* __restrict__ b0,
    const float* __restrict__ W1, const float* __restrict__ b1,
    int osel)
{
    __shared__ float As[32][68];
    __shared__ float Bs[32][256];

    const float* X = (xsel == 0) ? g_X0 : (xsel == 1) ? g_bufA : g_bufB;
    int ldx = (xsel == 0) ? XSTR : 128;
    float* H0 = (osel == 1) ? g_bufA : g_bufB;

    int tid = threadIdx.x;
    int row0 = blockIdx.x * 64;
    int rowg = tid & 7;          // 0..7
    int colg = tid >> 3;         // 0..15
    int r0 = rowg * 8;
    int c0 = colg * 16;

    unsigned long long acc[8][8];
#pragma unroll
    for (int i = 0; i < 8; i++)
#pragma unroll
        for (int j = 0; j < 8; j++) acc[i][j] = 0ULL;

    for (int kc = 0; kc < Kin; kc += 32) {
        int kmax = min(32, Kin - kc);
        // ---- A tile (64 rows x 32 cols), optional relu on load ----
#pragma unroll
        for (int i = 0; i < 4; i++) {
            int f4 = tid + i * 128;         // 0..511
            int r = f4 >> 3;
            int q = (f4 & 7) * 4;
            float4 v = make_float4(0.f, 0.f, 0.f, 0.f);
            int grow = row0 + r;
            if (grow < NV) {
                if (q + 3 < kmax) {
                    v = *(const float4*)&X[(size_t)grow * ldx + kc + q];
                } else {
                    float t0 = (q + 0 < kmax) ? X[(size_t)grow * ldx + kc + q + 0] : 0.f;
                    float t1 = (q + 1 < kmax) ? X[(size_t)grow * ldx + kc + q + 1] : 0.f;
                    float t2 = (q + 2 < kmax) ? X[(size_t)grow * ldx + kc + q + 2] : 0.f;
                    float t3 = (q + 3 < kmax) ? X[(size_t)grow * ldx + kc + q + 3] : 0.f;
                    v = make_float4(t0, t1, t2, t3);
                }
            }
            if (reluIn) {
                v.x = fmaxf(v.x, 0.f); v.y = fmaxf(v.y, 0.f);
                v.z = fmaxf(v.z, 0.f); v.w = fmaxf(v.w, 0.f);
            }
            As[q + 0][r] = v.x; As[q + 1][r] = v.y;
            As[q + 2][r] = v.z; As[q + 3][r] = v.w;
        }
        // ---- B tile (32 x 256 = W0 chunk | W1 chunk) ----
#pragma unroll
        for (int i = 0; i < 16; i++) {
            int f4 = tid + i * 128;         // 0..2047
            int k = f4 >> 6;
            int n4 = (f4 & 63) * 4;
            float4 v = make_float4(0.f, 0.f, 0.f, 0.f);
            if (k < kmax) {
                const float* Wp = (n4 < 128) ? W0 : W1;
                int nn = n4 & 127;
                v = *(const float4*)&Wp[(size_t)(kc + k) * 128 + nn];
            }
            *(float4*)&Bs[k][n4] = v;
        }
        __syncthreads();
#pragma unroll 2
        for (int k = 0; k < 32; k++) {
            float4 aA = *(const float4*)&As[k][r0];
            float4 aB = *(const float4*)&As[k][r0 + 4];
            unsigned long long ad[8] = {dup2(aA.x), dup2(aA.y), dup2(aA.z), dup2(aA.w),
                                        dup2(aB.x), dup2(aB.y), dup2(aB.z), dup2(aB.w)};
            ulonglong2 bp0 = *(const ulonglong2*)&Bs[k][c0];
            ulonglong2 bp1 = *(const ulonglong2*)&Bs[k][c0 + 4];
            ulonglong2 bp2 = *(const ulonglong2*)&Bs[k][c0 + 8];
            ulonglong2 bp3 = *(const ulonglong2*)&Bs[k][c0 + 12];
            unsigned long long bb[8] = {bp0.x, bp0.y, bp1.x, bp1.y,
                                        bp2.x, bp2.y, bp3.x, bp3.y};
#pragma unroll
            for (int i = 0; i < 8; i++)
#pragma unroll
                for (int j = 0; j < 8; j++) ffma2(acc[i][j], ad[i], bb[j]);
        }
        __syncthreads();
    }
    // ---- epilogue ----
    const float* bias;
    float* Hout;
    int cbase;
    if (colg < 8) { Hout = H0;   bias = b0; cbase = colg * 16; }
    else          { Hout = g_H1; bias = b1; cbase = (colg - 8) * 16; }
    float4 bv[4];
#pragma unroll
    for (int q = 0; q < 4; q++) bv[q] = *(const float4*)&bias[cbase + q * 4];
#pragma unroll
    for (int i = 0; i < 8; i++) {
        int grow = row0 + r0 + i;
        if (grow >= NV) continue;
        float* dst = &Hout[(size_t)grow * 128 + cbase];
#pragma unroll
        for (int q = 0; q < 4; q++) {
            float2 pA = unpk(acc[i][q * 2]);
            float2 pB = unpk(acc[i][q * 2 + 1]);
            float4 o = make_float4(pA.x + bv[q].x, pA.y + bv[q].y,
                                   pB.x + bv[q].z, pB.y + bv[q].w);
            *(float4*)&dst[q * 4] = o;
        }
    }
}

// =========================================================================
// Gather: OUT[v] (holding h0) += sum_{nb in adj(v)} g_H1[nb]
// osel: 1 -> g_bufA, 2 -> g_bufB
// =========================================================================
__global__ void gather_kernel(int osel)
{
    float* OUT = (osel == 1) ? g_bufA : g_bufB;
    int gwarp = (blockIdx.x * blockDim.x + threadIdx.x) >> 5;
    int lane = threadIdx.x & 31;
    if (gwarp >= NV) return;
    int v = gwarp;
    int s = g_offs[v], e = g_offs[v + 1];
    float4 acc = ((const float4*)&OUT[(size_t)v * 128])[lane];
    for (int i = s; i < e; i++) {
        int nb = g_entries[i];
        float4 h = ((const float4*)&g_H1[(size_t)nb * 128])[lane];
        acc.x += h.x; acc.y += h.y; acc.z += h.z; acc.w += h.w;
    }
    ((float4*)&OUT[(size_t)v * 128])[lane] = acc;
}

// =========================================================================
// Final projection: out = relu(X) @ off_w + off_b   (128 -> 3)
// =========================================================================
__global__ void final_kernel(int xsel,
                             const float* __restrict__ ow, const float* __restrict__ ob,
                             float* __restrict__ out)
{
    const float* X = (xsel == 1) ? g_bufA : g_bufB;
    int gwarp = (blockIdx.x * blockDim.x + threadIdx.x) >> 5;
    int lane = threadIdx.x & 31;
    if (gwarp >= NV) return;
    int v = gwarp;
    float4 x = ((const float4*)&X[(size_t)v * 128])[lane];
    x.x = fmaxf(x.x, 0.f); x.y = fmaxf(x.y, 0.f);
    x.z = fmaxf(x.z, 0.f); x.w = fmaxf(x.w, 0.f);
    const float* wr = &ow[(size_t)(lane * 4) * 3];
    float s0 = x.x * wr[0] + x.y * wr[3] + x.z * wr[6] + x.w * wr[9];
    float s1 = x.x * wr[1] + x.y * wr[4] + x.z * wr[7] + x.w * wr[10];
    float s2 = x.x * wr[2] + x.y * wr[5] + x.z * wr[8] + x.w * wr[11];
#pragma unroll
    for (int o = 16; o > 0; o >>= 1) {
        s0 += __shfl_down_sync(0xffffffffu, s0, o);
        s1 += __shfl_down_sync(0xffffffffu, s1, o);
        s2 += __shfl_down_sync(0xffffffffu, s2, o);
    }
    if (lane == 0) {
        out[(size_t)v * 3 + 0] = s0 + ob[0];
        out[(size_t)v * 3 + 1] = s1 + ob[1];
        out[(size_t)v * 3 + 2] = s2 + ob[2];
    }
}

// =========================================================================
extern "C" void kernel_launch(void* const* d_in, const int* in_sizes, int n_in,
                              void* d_out, int out_size)
{
    const float* f1   = (const float*)d_in[0];
    const float* f2   = (const float*)d_in[1];
    const float* f3   = (const float*)d_in[2];
    const float* f4   = (const float*)d_in[3];
    const float* av   = (const float*)d_in[4];
    const float* vp   = (const float*)d_in[5];
    const float* enc  = (const float*)d_in[6];
    const int*   edges = (const int*)d_in[7];     // int32 on device (jax x64 off)
    const float* bw   = (const float*)d_in[8];
    const float* bb   = (const float*)d_in[9];
    const float* g0w0 = (const float*)d_in[10];
    const float* g0b0 = (const float*)d_in[11];
    const float* g0w1 = (const float*)d_in[12];
    const float* g0b1 = (const float*)d_in[13];
    const float* gw0  = (const float*)d_in[14];
    const float* gb0  = (const float*)d_in[15];
    const float* gw1  = (const float*)d_in[16];
    const float* gb1  = (const float*)d_in[17];
    const float* ow   = (const float*)d_in[18];
    const float* ob   = (const float*)d_in[19];
    float* out = (float*)d_out;

    int E = in_sizes[7] / 2;   // element count / 2 ints per edge

    const int WARP_GRID = (NV + 7) / 8;   // 8 warps (vertices) per 256-thread block

    // P projection tables (direct store, no zeroing needed)
    precompute_kernel<<<268, 128>>>(f1, f2, f3, f4, bw);
    sampler_kernel<<<WARP_GRID, 256>>>(av, vp, enc, bb);

    // CSR build
    zero_cnt_kernel<<<(NV + 255) / 256, 256>>>();
    hist_kernel<<<(E + 255) / 256, 256>>>(edges, E);
    scan_kernel<<<1, 1024>>>();
    zero_cnt_kernel<<<(NV + 255) / 256, 256>>>();
    fill_kernel<<<(E + 255) / 256, 256>>>(edges, E);

    const int GEMM_GRID = (NV + 63) / 64;   // 641

    // layer 0 (Kin = 387, no relu on input), H0 -> bufA
    gemm_dual_kernel<<<GEMM_GRID, 128>>>(0, 387, 0, g0w0, g0b0, g0w1, g0b1, 1);
    gather_kernel<<<WARP_GRID, 256>>>(1);

    // layers 1..7 (Kin = 128, relu on input), ping-pong bufA <-> bufB
    int cur = 1, nxt = 2;
    for (int i = 0; i < 7; i++) {
        gemm_dual_kernel<<<GEMM_GRID, 128>>>(cur, 128, 1,
                                             gw0 + (size_t)i * 16384, gb0 + (size_t)i * 128,
                                             gw1 + (size_t)i * 16384, gb1 + (size_t)i * 128,
                                             nxt);
        gather_kernel<<<WARP_GRID, 256>>>(nxt);
        int t = cur; cur = nxt; nxt = t;
    }

    final_kernel<<<WARP_GRID, 256>>>(cur, ow, ob, out);
}

// round 7
// speedup vs baseline: 1.0908x; 1.0811x over previous
#include <cuda_runtime.h>
#include <cuda_bf16.h>
#include <cstdint>

#define NV   40968           // total vertices (B*V)
#define VPER 10242
#define XSTR 392             // padded row stride of X0 (387 used)
#define PTOT 2132480         // total floats in P tables

// P table offsets (floats) per feature map: B*HW*128 cumulative
#define POFF0 0
#define POFF1 1605632
#define POFF2 2007040
#define POFF3 2107392

// ---------------- device scratch (module globals; no allocations) --------
__device__ float g_P[PTOT];
__device__ float g_X0[(size_t)NV * XSTR];
__device__ float g_bufA[(size_t)NV * 128];
__device__ float g_bufB[(size_t)NV * 128];
__device__ float g_H1[(size_t)NV * 128];
__device__ int   g_cnt[NV];
__device__ int   g_offs[NV + 1];
__device__ int   g_entries[245760];

// ---------------- helpers ----------------
__device__ __forceinline__ unsigned long long dup2(float x) {
    unsigned long long r;
    asm("mov.b64 %0, {%1, %1};" : "=l"(r) : "f"(x));
    return r;
}
__device__ __forceinline__ void ffma2(unsigned long long &d, unsigned long long a, unsigned long long b) {
    asm("fma.rn.f32x2 %0, %1, %2, %0;" : "+l"(d) : "l"(a), "l"(b));
}
__device__ __forceinline__ float2 unpk(unsigned long long v) {
    float2 r;
    asm("mov.b64 {%0, %1}, %2;" : "=f"(r.x), "=f"(r.y) : "l"(v));
    return r;
}
__device__ __forceinline__ float tf32r(float x) {
    uint32_t u;
    asm("cvt.rna.tf32.f32 %0, %1;" : "=r"(u) : "f"(x));
    return __uint_as_float(u);
}
__device__ __forceinline__ void mma_tf32(float* d, const uint32_t* a, const uint32_t* b) {
    asm("mma.sync.aligned.m16n8k8.row.col.f32.tf32.tf32.f32 "
        "{%0,%1,%2,%3},{%4,%5,%6,%7},{%8,%9},{%0,%1,%2,%3};"
        : "+f"(d[0]), "+f"(d[1]), "+f"(d[2]), "+f"(d[3])
        : "r"(a[0]), "r"(a[1]), "r"(a[2]), "r"(a[3]), "r"(b[0]), "r"(b[1]));
}

// =========================================================================
// zero kernels
// =========================================================================
__global__ void zero_cnt_kernel()
{
    int i = blockIdx.x * blockDim.x + threadIdx.x;
    if (i < NV) g_cnt[i] = 0;
}
__global__ void zero_P_kernel()
{
    int i = blockIdx.x * blockDim.x + threadIdx.x;   // float4 index
    if (i < PTOT / 4) ((float4*)g_P)[i] = make_float4(0.f, 0.f, 0.f, 0.f);
}

// =========================================================================
// Kernel 1: per-pixel projection, split-K balanced (396 blocks x 8 chunks),
// atomicAdd epilogue into zeroed P. 64px x 128 outputs, f32x2 micro.
// =========================================================================
__global__ void __launch_bounds__(128) precompute_kernel(
    const float* __restrict__ f1, const float* __restrict__ f2,
    const float* __restrict__ f3, const float* __restrict__ f4,
    const float* __restrict__ BW)
{
    __shared__ float As[32][68];
    __shared__ float Bs[32][128];

    int bid = blockIdx.x;
    int m, local;
    if (bid < 196)      { m = 0; local = bid; }          // 49mt*4b*1ks
    else if (bid < 300) { m = 1; local = bid - 196; }    // 13mt*4b*2ks
    else if (bid < 364) { m = 2; local = bid - 300; }    // 4mt*4b*4ks
    else                { m = 3; local = bid - 364; }    // 1mt*4b*8ks

    const float* fm;
    int HW, C, WO, ks; size_t poff;
    if (m == 0)      { fm = f1; HW = 3136; C = 256;  WO = 0;    poff = POFF0; ks = 1; }
    else if (m == 1) { fm = f2; HW = 784;  C = 512;  WO = 256;  poff = POFF1; ks = 2; }
    else if (m == 2) { fm = f3; HW = 196;  C = 1024; WO = 768;  poff = POFF2; ks = 4; }
    else             { fm = f4; HW = 49;   C = 2048; WO = 1792; poff = POFF3; ks = 8; }

    int kt   = local % ks;
    int rest = local / ks;
    int b  = rest & 3;
    int mt = rest >> 2;

    int p0  = mt * 64;
    int kc0 = kt * 256;
    int tid = threadIdx.x;
    int rowg = tid & 7;
    int colg = tid >> 3;
    int r0 = rowg * 8;
    int c0 = colg * 8;

    unsigned long long acc[8][4];
#pragma unroll
    for (int i = 0; i < 8; i++)
#pragma unroll
        for (int j = 0; j < 4; j++) acc[i][j] = 0ULL;

    for (int ch = 0; ch < 8; ch++) {
        int kk = kc0 + ch * 32;
#pragma unroll
        for (int i = 0; i < 16; i++) {
            int lin = tid + i * 128;
            int c = lin >> 6;
            int p = lin & 63;
            float v = 0.f;
            if (p0 + p < HW)
                v = fm[((size_t)b * C + (kk + c)) * HW + p0 + p];
            As[c][p] = v;
        }
#pragma unroll
        for (int i = 0; i < 8; i++) {
            int lin4 = tid + i * 128;
            int k = lin4 >> 5;
            int n4 = (lin4 & 31) * 4;
            float4 v = *(const float4*)&BW[(size_t)(WO + kk + k) * 128 + n4];
            *(float4*)&Bs[k][n4] = v;
        }
        __syncthreads();
#pragma unroll 2
        for (int k = 0; k < 32; k++) {
            float4 aA = *(const float4*)&As[k][r0];
            float4 aB = *(const float4*)&As[k][r0 + 4];
            unsigned long long ad[8] = {dup2(aA.x), dup2(aA.y), dup2(aA.z), dup2(aA.w),
                                        dup2(aB.x), dup2(aB.y), dup2(aB.z), dup2(aB.w)};
            ulonglong2 bp0 = *(const ulonglong2*)&Bs[k][c0];
            ulonglong2 bp1 = *(const ulonglong2*)&Bs[k][c0 + 4];
            unsigned long long bb[4] = {bp0.x, bp0.y, bp1.x, bp1.y};
#pragma unroll
            for (int i = 0; i < 8; i++)
#pragma unroll
                for (int j = 0; j < 4; j++) ffma2(acc[i][j], ad[i], bb[j]);
        }
        __syncthreads();
    }
    // epilogue: atomic accumulate (split-K)
    size_t pbase = poff + (size_t)b * HW * 128;
#pragma unroll
    for (int i = 0; i < 8; i++) {
        int pix = p0 + r0 + i;
        if (pix >= HW) continue;
        float* dst = &g_P[pbase + (size_t)pix * 128 + c0];
        if (ks == 1) {
#pragma unroll
            for (int j = 0; j < 2; j++) {
                float2 vA = unpk(acc[i][j * 2]);
                float2 vB = unpk(acc[i][j * 2 + 1]);
                *(float4*)&dst[j * 4] = make_float4(vA.x, vA.y, vB.x, vB.y);
            }
        } else {
#pragma unroll
            for (int j = 0; j < 4; j++) {
                float2 v = unpk(acc[i][j]);
                atomicAdd(&dst[j * 2 + 0], v.x);
                atomicAdd(&dst[j * 2 + 1], v.y);
            }
        }
    }
}

// =========================================================================
// Kernel 2: bilinear sampler + bias + relu + assemble X0 row
// =========================================================================
__global__ void sampler_kernel(
    const float* __restrict__ av, const float* __restrict__ vp,
    const float* __restrict__ enc, const float* __restrict__ bias)
{
    int gwarp = (blockIdx.x * blockDim.x + threadIdx.x) >> 5;
    int lane = threadIdx.x & 31;
    if (gwarp >= NV) return;
    int v = gwarp;
    int b = v / VPER;

    float gx = av[(size_t)v * 3 + 0];
    float gy = av[(size_t)v * 3 + 1];

    float4 acc = make_float4(0.f, 0.f, 0.f, 0.f);
#pragma unroll
    for (int m = 0; m < 4; m++) {
        const int DIMm = (m == 0) ? 56 : (m == 1) ? 28 : (m == 2) ? 14 : 7;
        const int HWm  = DIMm * DIMm;
        const size_t POm = (m == 0) ? POFF0 : (m == 1) ? POFF1 : (m == 2) ? POFF2 : POFF3;
        int w = DIMm;
        float fx = (gx + 1.f) * 0.5f * (float)(w - 1);
        float fy = (gy + 1.f) * 0.5f * (float)(w - 1);
        float x0f = floorf(fx), y0f = floorf(fy);
        float wx1 = fx - x0f, wy1 = fy - y0f;
        float wx0 = 1.f - wx1, wy0 = 1.f - wy1;
        int x0 = min(max((int)x0f, 0), w - 1);
        int x1 = min(max((int)x0f + 1, 0), w - 1);
        int y0 = min(max((int)y0f, 0), w - 1);
        int y1 = min(max((int)y0f + 1, 0), w - 1);
        size_t base = POm + (size_t)b * HWm * 128;
        float4 c00 = ((const float4*)&g_P[base + (size_t)(y0 * w + x0) * 128])[lane];
        float4 c01 = ((const float4*)&g_P[base + (size_t)(y0 * w + x1) * 128])[lane];
        float4 c10 = ((const float4*)&g_P[base + (size_t)(y1 * w + x0) * 128])[lane];
        float4 c11 = ((const float4*)&g_P[base + (size_t)(y1 * w + x1) * 128])[lane];
        float w00 = wy0 * wx0, w01 = wy0 * wx1, w10 = wy1 * wx0, w11 = wy1 * wx1;
        acc.x += w00 * c00.x + w01 * c01.x + w10 * c10.x + w11 * c11.x;
        acc.y += w00 * c00.y + w01 * c01.y + w10 * c10.y + w11 * c11.y;
        acc.z += w00 * c00.z + w01 * c01.z + w10 * c10.z + w11 * c11.z;
        acc.w += w00 * c00.w + w01 * c01.w + w10 * c10.w + w11 * c11.w;
    }
    float4 bb = ((const float4*)bias)[lane];
    acc.x = fmaxf(acc.x + bb.x, 0.f);
    acc.y = fmaxf(acc.y + bb.y, 0.f);
    acc.z = fmaxf(acc.z + bb.z, 0.f);
    acc.w = fmaxf(acc.w + bb.w, 0.f);
    float* row = &g_X0[(size_t)v * XSTR];
    ((float4*)row)[lane] = acc;
    if (lane < 3) row[128 + lane] = vp[(size_t)v * 3 + lane];
#pragma unroll
    for (int j = 0; j < 8; j++)
        row[131 + lane * 8 + j] = enc[(size_t)b * 256 + lane * 8 + j];
}

// =========================================================================
// CSR build  (edges are INT32 on device)
// =========================================================================
__global__ void hist_kernel(const int* __restrict__ edges, int E)
{
    int i = blockIdx.x * blockDim.x + threadIdx.x;
    if (i >= E) return;
    atomicAdd(&g_cnt[edges[2 * i]], 1);
    atomicAdd(&g_cnt[edges[2 * i + 1]], 1);
}

__global__ void scan_kernel()
{
    __shared__ int part[1024];
    const int n = NV;
    int t = threadIdx.x;
    int chunk = (n + 1023) >> 10;
    int base = t * chunk;
    int sum = 0;
    for (int j = 0; j < chunk; j++) {
        int idx = base + j;
        if (idx < n) sum += g_cnt[idx];
    }
    part[t] = sum;
    __syncthreads();
    for (int off = 1; off < 1024; off <<= 1) {
        int v = 0;
        if (t >= off) v = part[t - off];
        __syncthreads();
        part[t] += v;
        __syncthreads();
    }
    int run = part[t] - sum;
    for (int j = 0; j < chunk; j++) {
        int idx = base + j;
        if (idx < n) { g_offs[idx] = run; run += g_cnt[idx]; }
    }
    if (t == 1023) g_offs[n] = part[1023];
}

__global__ void fill_kernel(const int* __restrict__ edges, int E)
{
    int i = blockIdx.x * blockDim.x + threadIdx.x;
    if (i >= E) return;
    int v0 = edges[2 * i];
    int v1 = edges[2 * i + 1];
    int p0 = atomicAdd(&g_cnt[v0], 1);
    g_entries[g_offs[v0] + p0] = v1;
    int p1 = atomicAdd(&g_cnt[v1], 1);
    g_entries[g_offs[v1] + p1] = v0;
}

// =========================================================================
// 3xTF32 tensor-core dual GEMM (near-fp32 precision):
//   H0 = act(X)@W0+b0 ; g_H1 = act(X)@W1+b1
// BM=128, BN=256, BK=32. 512 threads = 16 warps (2 m x 8 n), warp 64x32.
// Each operand split hi/lo (tf32); d += ah*bl + al*bh + ah*bh.
// =========================================================================
#define SM_A_BLK 132   // padded floats per (Mi,Ks) fragment block
#define SM_B_BLK 66
#define SM_A_TOT (32 * SM_A_BLK)    // 4224 floats
#define SM_B_TOT (128 * SM_B_BLK)   // 8448 floats
#define SMEM_GEMM_BYTES ((SM_A_TOT + SM_B_TOT) * 2 * 4)   // hi+lo

__global__ void __launch_bounds__(512, 1) gemm_dual_tf32x3(
    int xsel, int Kin, int reluIn,
    const float* __restrict__ W0, const float* __restrict__ b0,
    const float* __restrict__ W1, const float* __restrict__ b1,
    int osel)
{
    extern __shared__ float smem[];
    float* sAh = smem;
    float* sAl = smem + SM_A_TOT;
    float* sBh = smem + 2 * SM_A_TOT;
    float* sBl = smem + 2 * SM_A_TOT + SM_B_TOT;

    const float* X = (xsel == 0) ? g_X0 : (xsel == 1) ? g_bufA : g_bufB;
    int ldx = (xsel == 0) ? XSTR : 128;
    float* H0 = (osel == 1) ? g_bufA : g_bufB;

    int tid = threadIdx.x;
    int lane = tid & 31;
    int wid = tid >> 5;
    int warp_m = wid >> 3;    // 0..1 -> rows 0-63 / 64-127
    int warp_n = wid & 7;     // 0..7 -> 32-col slabs over 256
    int row0 = blockIdx.x * 128;

    float d[4][4][4];
#pragma unroll
    for (int mt = 0; mt < 4; mt++)
#pragma unroll
        for (int nt = 0; nt < 4; nt++)
#pragma unroll
            for (int q = 0; q < 4; q++) d[mt][nt][q] = 0.f;

    for (int kc = 0; kc < Kin; kc += 32) {
        int kmax = min(32, Kin - kc);
        // ---- stage A (128 rows x 32 k) hi/lo into fragment layout ----
#pragma unroll
        for (int i = 0; i < 2; i++) {
            int f4 = tid + i * 512;          // 0..1023
            int r  = f4 >> 3;                // 0..127
            int c4 = (f4 & 7) * 4;
            int grow = row0 + r;
            float vv[4] = {0.f, 0.f, 0.f, 0.f};
            if (grow < NV) {
                if (c4 + 3 < kmax) {
                    float4 v = *(const float4*)&X[(size_t)grow * ldx + kc + c4];
                    vv[0] = v.x; vv[1] = v.y; vv[2] = v.z; vv[3] = v.w;
                } else {
#pragma unroll
                    for (int j = 0; j < 4; j++)
                        if (c4 + j < kmax) vv[j] = X[(size_t)grow * ldx + kc + c4 + j];
                }
            }
#pragma unroll
            for (int j = 0; j < 4; j++) {
                float x = vv[j];
                if (reluIn) x = fmaxf(x, 0.f);
                float hi = tf32r(x);
                float lo = tf32r(x - hi);
                int c  = c4 + j;
                int Mi = r >> 4, Ks = c >> 3;
                int rr = r & 15, cc = c & 7;
                int ln = (rr & 7) * 4 + (cc & 3);
                int rg = (rr >> 3) + 2 * (cc >> 2);
                int idx = (Mi * 4 + Ks) * SM_A_BLK + ln * 4 + rg;
                sAh[idx] = hi;
                sAl[idx] = lo;
            }
        }
        // ---- stage B (32 k x 256 n = W0|W1) hi/lo ----
#pragma unroll
        for (int i = 0; i < 4; i++) {
            int f4 = tid + i * 512;          // 0..2047
            int k  = f4 >> 6;                // 0..31
            int c4 = (f4 & 63) * 4;          // 0..252
            float vv[4] = {0.f, 0.f, 0.f, 0.f};
            if (k < kmax) {
                const float* Wp = (c4 < 128) ? W0 : W1;
                int nn = c4 & 127;
                float4 v = *(const float4*)&Wp[(size_t)(kc + k) * 128 + nn];
                vv[0] = v.x; vv[1] = v.y; vv[2] = v.z; vv[3] = v.w;
            }
#pragma unroll
            for (int j = 0; j < 4; j++) {
                float x = vv[j];
                float hi = tf32r(x);
                float lo = tf32r(x - hi);
                int c  = c4 + j;
                int Ni = c >> 3, Ks = k >> 3;
                int kk = k & 7,  cc = c & 7;
                int ln = cc * 4 + (kk & 3);
                int rg = kk >> 2;
                int idx = (Ni * 4 + Ks) * SM_B_BLK + ln * 2 + rg;
                sBh[idx] = hi;
                sBl[idx] = lo;
            }
        }
        __syncthreads();
        // ---- compute: 4 k-steps of m16n8k8, 3 passes each ----
#pragma unroll
        for (int Ks = 0; Ks < 4; Ks++) {
            uint32_t ah[4][4], al[4][4];
#pragma unroll
            for (int mt = 0; mt < 4; mt++) {
                int Mi = warp_m * 4 + mt;
                int base = (Mi * 4 + Ks) * SM_A_BLK + lane * 4;
                float4 th = *(const float4*)&sAh[base];
                float4 tl = *(const float4*)&sAl[base];
                ah[mt][0] = __float_as_uint(th.x); ah[mt][1] = __float_as_uint(th.y);
                ah[mt][2] = __float_as_uint(th.z); ah[mt][3] = __float_as_uint(th.w);
                al[mt][0] = __float_as_uint(tl.x); al[mt][1] = __float_as_uint(tl.y);
                al[mt][2] = __float_as_uint(tl.z); al[mt][3] = __float_as_uint(tl.w);
            }
#pragma unroll
            for (int nt = 0; nt < 4; nt++) {
                int Ni = warp_n * 4 + nt;
                int base = (Ni * 4 + Ks) * SM_B_BLK + lane * 2;
                float2 th = *(const float2*)&sBh[base];
                float2 tl = *(const float2*)&sBl[base];
                uint32_t bh[2] = {__float_as_uint(th.x), __float_as_uint(th.y)};
                uint32_t bl[2] = {__float_as_uint(tl.x), __float_as_uint(tl.y)};
#pragma unroll
                for (int mt = 0; mt < 4; mt++) {
                    mma_tf32(d[mt][nt], ah[mt], bl);
                    mma_tf32(d[mt][nt], al[mt], bh);
                    mma_tf32(d[mt][nt], ah[mt], bh);
                }
            }
        }
        __syncthreads();
    }
    // ---- epilogue ----
#pragma unroll
    for (int nt = 0; nt < 4; nt++) {
        int gcol = warp_n * 32 + nt * 8;
        float* Hout; const float* bias; int cb;
        if (gcol < 128) { Hout = H0;   bias = b0; cb = gcol; }
        else            { Hout = g_H1; bias = b1; cb = gcol - 128; }
        int c0 = cb + (lane & 3) * 2;
        float2 bv = *(const float2*)&bias[c0];
#pragma unroll
        for (int mt = 0; mt < 4; mt++) {
            int rtop = row0 + warp_m * 64 + mt * 16 + (lane >> 2);
            if (rtop < NV) {
                float2 o = make_float2(d[mt][nt][0] + bv.x, d[mt][nt][1] + bv.y);
                *(float2*)&Hout[(size_t)rtop * 128 + c0] = o;
            }
            int rbot = rtop + 8;
            if (rbot < NV) {
                float2 o = make_float2(d[mt][nt][2] + bv.x, d[mt][nt][3] + bv.y);
                *(float2*)&Hout[(size_t)rbot * 128 + c0] = o;
            }
        }
    }
}

// =========================================================================
// Gather: OUT[v] (holding h0) += sum_{nb in adj(v)} g_H1[nb]
// =========================================================================
__global__ void gather_kernel(int osel)
{
    float* OUT = (osel == 1) ? g_bufA : g_bufB;
    int gwarp = (blockIdx.x * blockDim.x + threadIdx.x) >> 5;
    int lane = threadIdx.x & 31;
    if (gwarp >= NV) return;
    int v = gwarp;
    int s = g_offs[v], e = g_offs[v + 1];
    float4 acc = ((const float4*)&OUT[(size_t)v * 128])[lane];
    for (int i = s; i < e; i++) {
        int nb = g_entries[i];
        float4 h = ((const float4*)&g_H1[(size_t)nb * 128])[lane];
        acc.x += h.x; acc.y += h.y; acc.z += h.z; acc.w += h.w;
    }
    ((float4*)&OUT[(size_t)v * 128])[lane] = acc;
}

// =========================================================================
// Final projection: out = relu(X) @ off_w + off_b   (128 -> 3)
// =========================================================================
__global__ void final_kernel(int xsel,
                             const float* __restrict__ ow, const float* __restrict__ ob,
                             float* __restrict__ out)
{
    const float* X = (xsel == 1) ? g_bufA : g_bufB;
    int gwarp = (blockIdx.x * blockDim.x + threadIdx.x) >> 5;
    int lane = threadIdx.x & 31;
    if (gwarp >= NV) return;
    int v = gwarp;
    float4 x = ((const float4*)&X[(size_t)v * 128])[lane];
    x.x = fmaxf(x.x, 0.f); x.y = fmaxf(x.y, 0.f);
    x.z = fmaxf(x.z, 0.f); x.w = fmaxf(x.w, 0.f);
    const float* wr = &ow[(size_t)(lane * 4) * 3];
    float s0 = x.x * wr[0] + x.y * wr[3] + x.z * wr[6] + x.w * wr[9];
    float s1 = x.x * wr[1] + x.y * wr[4] + x.z * wr[7] + x.w * wr[10];
    float s2 = x.x * wr[2] + x.y * wr[5] + x.z * wr[8] + x.w * wr[11];
#pragma unroll
    for (int o = 16; o > 0; o >>= 1) {
        s0 += __shfl_down_sync(0xffffffffu, s0, o);
        s1 += __shfl_down_sync(0xffffffffu, s1, o);
        s2 += __shfl_down_sync(0xffffffffu, s2, o);
    }
    if (lane == 0) {
        out[(size_t)v * 3 + 0] = s0 + ob[0];
        out[(size_t)v * 3 + 1] = s1 + ob[1];
        out[(size_t)v * 3 + 2] = s2 + ob[2];
    }
}

// =========================================================================
extern "C" void kernel_launch(void* const* d_in, const int* in_sizes, int n_in,
                              void* d_out, int out_size)
{
    const float* f1   = (const float*)d_in[0];
    const float* f2   = (const float*)d_in[1];
    const float* f3   = (const float*)d_in[2];
    const float* f4   = (const float*)d_in[3];
    const float* av   = (const float*)d_in[4];
    const float* vp   = (const float*)d_in[5];
    const float* enc  = (const float*)d_in[6];
    const int*   edges = (const int*)d_in[7];     // int32 on device (jax x64 off)
    const float* bw   = (const float*)d_in[8];
    const float* bb   = (const float*)d_in[9];
    const float* g0w0 = (const float*)d_in[10];
    const float* g0b0 = (const float*)d_in[11];
    const float* g0w1 = (const float*)d_in[12];
    const float* g0b1 = (const float*)d_in[13];
    const float* gw0  = (const float*)d_in[14];
    const float* gb0  = (const float*)d_in[15];
    const float* gw1  = (const float*)d_in[16];
    const float* gb1  = (const float*)d_in[17];
    const float* ow   = (const float*)d_in[18];
    const float* ob   = (const float*)d_in[19];
    float* out = (float*)d_out;

    int E = in_sizes[7] / 2;

    cudaFuncSetAttribute(gemm_dual_tf32x3,
                         cudaFuncAttributeMaxDynamicSharedMemorySize,
                         SMEM_GEMM_BYTES);

    const int WARP_GRID = (NV + 7) / 8;

    // P projection tables (split-K -> zero first)
    zero_P_kernel<<<(PTOT / 4 + 255) / 256, 256>>>();
    precompute_kernel<<<396, 128>>>(f1, f2, f3, f4, bw);
    sampler_kernel<<<WARP_GRID, 256>>>(av, vp, enc, bb);

    // CSR build
    zero_cnt_kernel<<<(NV + 255) / 256, 256>>>();
    hist_kernel<<<(E + 255) / 256, 256>>>(edges, E);
    scan_kernel<<<1, 1024>>>();
    zero_cnt_kernel<<<(NV + 255) / 256, 256>>>();
    fill_kernel<<<(E + 255) / 256, 256>>>(edges, E);

    const int GEMM_GRID = (NV + 127) / 128;   // 321

    // layer 0 (Kin = 387, no relu on input), H0 -> bufA
    gemm_dual_tf32x3<<<GEMM_GRID, 512, SMEM_GEMM_BYTES>>>(0, 387, 0,
                                                          g0w0, g0b0, g0w1, g0b1, 1);
    gather_kernel<<<WARP_GRID, 256>>>(1);

    // layers 1..7 (Kin = 128, relu on input), ping-pong bufA <-> bufB
    int cur = 1, nxt = 2;
    for (int i = 0; i < 7; i++) {
        gemm_dual_tf32x3<<<GEMM_GRID, 512, SMEM_GEMM_BYTES>>>(cur, 128, 1,
                                             gw0 + (size_t)i * 16384, gb0 + (size_t)i * 128,
                                             gw1 + (size_t)i * 16384, gb1 + (size_t)i * 128,
                                             nxt);
        gather_kernel<<<WARP_GRID, 256>>>(nxt);
        int t = cur; cur = nxt; nxt = t;
    }

    final_kernel<<<WARP_GRID, 256>>>(cur, ow, ob, out);
}

// round 9
// speedup vs baseline: 1.7460x; 1.6007x over previous
#include <cuda_runtime.h>
#include <cuda_bf16.h>
#include <cuda_fp16.h>
#include <cstdint>

#define NV   40968           // total vertices (B*V)
#define VPER 10242
#define XSTR 392             // padded row stride of X0 (387 used)
#define PTOT 2132480         // total floats in P tables

// P table offsets (floats) per feature map: B*HW*128 cumulative
#define POFF0 0
#define POFF1 1605632
#define POFF2 2007040
#define POFF3 2107392

// weight images: 41 images (layer0: 13 chunks, layers1-7: 4 each), each
// 8192 uint32 words (hi 4096 | lo 4096) in mma fragment layout.
#define NIMG 41

// ---------------- device scratch (module globals; no allocations) --------
__device__ float g_P[PTOT];
__device__ float g_X0[(size_t)NV * XSTR];
__device__ float g_bufA[(size_t)NV * 128];
__device__ float g_bufB[(size_t)NV * 128];
__device__ float g_H1[(size_t)NV * 128];
__device__ int   g_cnt[NV];
__device__ int   g_offs[NV + 1];
__device__ int   g_entries[245760];
__device__ __align__(16) uint32_t g_pack[NIMG * 8192];

// ---------------- f32x2 helpers (precompute kernel) ----------------
__device__ __forceinline__ unsigned long long dup2(float x) {
    unsigned long long r;
    asm("mov.b64 %0, {%1, %1};" : "=l"(r) : "f"(x));
    return r;
}
__device__ __forceinline__ void ffma2(unsigned long long &d, unsigned long long a, unsigned long long b) {
    asm("fma.rn.f32x2 %0, %1, %2, %0;" : "+l"(d) : "l"(a), "l"(b));
}
__device__ __forceinline__ float2 unpk(unsigned long long v) {
    float2 r;
    asm("mov.b64 {%0, %1}, %2;" : "=f"(r.x), "=f"(r.y) : "l"(v));
    return r;
}

// fp16 mma m16n8k16, f32 accumulate
__device__ __forceinline__ void mma_f16(float* d, const uint32_t* a, const uint32_t* b) {
    asm("mma.sync.aligned.m16n8k16.row.col.f32.f16.f16.f32 "
        "{%0,%1,%2,%3},{%4,%5,%6,%7},{%8,%9},{%0,%1,%2,%3};"
        : "+f"(d[0]), "+f"(d[1]), "+f"(d[2]), "+f"(d[3])
        : "r"(a[0]), "r"(a[1]), "r"(a[2]), "r"(a[3]), "r"(b[0]), "r"(b[1]));
}
__device__ __forceinline__ uint32_t pack_h2(__half a, __half b) {
    __half2 h2 = __halves2half2(a, b);
    return *(uint32_t*)&h2;
}

// =========================================================================
// zero kernels
// =========================================================================
__global__ void zero_cnt_kernel()
{
    int i = blockIdx.x * blockDim.x + threadIdx.x;
    if (i < NV) g_cnt[i] = 0;
}
__global__ void zero_P_kernel()
{
    int i = blockIdx.x * blockDim.x + threadIdx.x;
    if (i < PTOT / 4) ((float4*)g_P)[i] = make_float4(0.f, 0.f, 0.f, 0.f);
}

// =========================================================================
// Weight prepack: (layer, k-chunk32) -> fragment-layout hi/lo fp16 images.
// B fragment (m16n8k16, col-major): lane = nn*4 + t, b0 = (k=2t, 2t+1),
// b1 = (k=2t+8, 2t+9); word = ((Ni*2+Ks)*32 + nn*4 + t)*2 + rg.
// =========================================================================
__global__ void prepack_weights(
    const float* __restrict__ g0w0, const float* __restrict__ g0w1,
    const float* __restrict__ gw0,  const float* __restrict__ gw1)
{
    int idx = blockIdx.x * 256 + threadIdx.x;
    if (idx >= NIMG * 4096) return;
    int img = idx >> 12;
    int e   = idx & 4095;
    int n   = e >> 4;          // 0..255
    int kp  = e & 15;          // k-pair 0..15 (k = 2*kp)

    const float *W0, *W1; int Kin, chunk;
    if (img < 13) { W0 = g0w0; W1 = g0w1; Kin = 387; chunk = img; }
    else {
        int t = img - 13;
        int L = t >> 2; chunk = t & 3;
        W0 = gw0 + (size_t)L * 16384;
        W1 = gw1 + (size_t)L * 16384;
        Kin = 128;
    }
    const float* W = (n < 128) ? W0 : W1;
    int col = n & 127;
    int kg = chunk * 32 + kp * 2;
    float w0v = (kg     < Kin) ? W[(size_t)kg * 128 + col]       : 0.f;
    float w1v = (kg + 1 < Kin) ? W[(size_t)(kg + 1) * 128 + col] : 0.f;

    __half h0 = __float2half_rn(w0v);
    __half l0 = __float2half_rn(w0v - __half2float(h0));
    __half h1 = __float2half_rn(w1v);
    __half l1 = __float2half_rn(w1v - __half2float(h1));

    int Ni = n >> 3, nn = n & 7;
    int kk = kp * 2;
    int Ks = kk >> 4;
    int kk16 = kk & 15;
    int rg = (kk16 >= 8) ? 1 : 0;
    int t  = (kk16 & 7) >> 1;
    int word = ((Ni * 2 + Ks) * 32 + nn * 4 + t) * 2 + rg;
    size_t base = (size_t)img * 8192;
    g_pack[base + word]        = pack_h2(h0, h1);
    g_pack[base + 4096 + word] = pack_h2(l0, l1);
}

// =========================================================================
// Kernel 1: per-pixel projection, split-K balanced, atomicAdd epilogue.
// =========================================================================
__global__ void __launch_bounds__(128) precompute_kernel(
    const float* __restrict__ f1, const float* __restrict__ f2,
    const float* __restrict__ f3, const float* __restrict__ f4,
    const float* __restrict__ BW)
{
    __shared__ float As[32][68];
    __shared__ float Bs[32][128];

    int bid = blockIdx.x;
    int m, local;
    if (bid < 196)      { m = 0; local = bid; }
    else if (bid < 300) { m = 1; local = bid - 196; }
    else if (bid < 364) { m = 2; local = bid - 300; }
    else                { m = 3; local = bid - 364; }

    const float* fm;
    int HW, C, WO, ks; size_t poff;
    if (m == 0)      { fm = f1; HW = 3136; C = 256;  WO = 0;    poff = POFF0; ks = 1; }
    else if (m == 1) { fm = f2; HW = 784;  C = 512;  WO = 256;  poff = POFF1; ks = 2; }
    else if (m == 2) { fm = f3; HW = 196;  C = 1024; WO = 768;  poff = POFF2; ks = 4; }
    else             { fm = f4; HW = 49;   C = 2048; WO = 1792; poff = POFF3; ks = 8; }

    int kt   = local % ks;
    int rest = local / ks;
    int b  = rest & 3;
    int mt = rest >> 2;

    int p0  = mt * 64;
    int kc0 = kt * 256;
    int tid = threadIdx.x;
    int rowg = tid & 7;
    int colg = tid >> 3;
    int r0 = rowg * 8;
    int c0 = colg * 8;

    unsigned long long acc[8][4];
#pragma unroll
    for (int i = 0; i < 8; i++)
#pragma unroll
        for (int j = 0; j < 4; j++) acc[i][j] = 0ULL;

    for (int ch = 0; ch < 8; ch++) {
        int kk = kc0 + ch * 32;
#pragma unroll
        for (int i = 0; i < 16; i++) {
            int lin = tid + i * 128;
            int c = lin >> 6;
            int p = lin & 63;
            float v = 0.f;
            if (p0 + p < HW)
                v = fm[((size_t)b * C + (kk + c)) * HW + p0 + p];
            As[c][p] = v;
        }
#pragma unroll
        for (int i = 0; i < 8; i++) {
            int lin4 = tid + i * 128;
            int k = lin4 >> 5;
            int n4 = (lin4 & 31) * 4;
            float4 v = *(const float4*)&BW[(size_t)(WO + kk + k) * 128 + n4];
            *(float4*)&Bs[k][n4] = v;
        }
        __syncthreads();
#pragma unroll 2
        for (int k = 0; k < 32; k++) {
            float4 aA = *(const float4*)&As[k][r0];
            float4 aB = *(const float4*)&As[k][r0 + 4];
            unsigned long long ad[8] = {dup2(aA.x), dup2(aA.y), dup2(aA.z), dup2(aA.w),
                                        dup2(aB.x), dup2(aB.y), dup2(aB.z), dup2(aB.w)};
            ulonglong2 bp0 = *(const ulonglong2*)&Bs[k][c0];
            ulonglong2 bp1 = *(const ulonglong2*)&Bs[k][c0 + 4];
            unsigned long long bb[4] = {bp0.x, bp0.y, bp1.x, bp1.y};
#pragma unroll
            for (int i = 0; i < 8; i++)
#pragma unroll
                for (int j = 0; j < 4; j++) ffma2(acc[i][j], ad[i], bb[j]);
        }
        __syncthreads();
    }
    size_t pbase = poff + (size_t)b * HW * 128;
#pragma unroll
    for (int i = 0; i < 8; i++) {
        int pix = p0 + r0 + i;
        if (pix >= HW) continue;
        float* dst = &g_P[pbase + (size_t)pix * 128 + c0];
        if (ks == 1) {
#pragma unroll
            for (int j = 0; j < 2; j++) {
                float2 vA = unpk(acc[i][j * 2]);
                float2 vB = unpk(acc[i][j * 2 + 1]);
                *(float4*)&dst[j * 4] = make_float4(vA.x, vA.y, vB.x, vB.y);
            }
        } else {
#pragma unroll
            for (int j = 0; j < 4; j++) {
                float2 v = unpk(acc[i][j]);
                atomicAdd(&dst[j * 2 + 0], v.x);
                atomicAdd(&dst[j * 2 + 1], v.y);
            }
        }
    }
}

// =========================================================================
// Kernel 2: bilinear sampler + bias + relu + assemble X0 row
// =========================================================================
__global__ void sampler_kernel(
    const float* __restrict__ av, const float* __restrict__ vp,
    const float* __restrict__ enc, const float* __restrict__ bias)
{
    int gwarp = (blockIdx.x * blockDim.x + threadIdx.x) >> 5;
    int lane = threadIdx.x & 31;
    if (gwarp >= NV) return;
    int v = gwarp;
    int b = v / VPER;

    float gx = av[(size_t)v * 3 + 0];
    float gy = av[(size_t)v * 3 + 1];

    float4 acc = make_float4(0.f, 0.f, 0.f, 0.f);
#pragma unroll
    for (int m = 0; m < 4; m++) {
        const int DIMm = (m == 0) ? 56 : (m == 1) ? 28 : (m == 2) ? 14 : 7;
        const int HWm  = DIMm * DIMm;
        const size_t POm = (m == 0) ? POFF0 : (m == 1) ? POFF1 : (m == 2) ? POFF2 : POFF3;
        int w = DIMm;
        float fx = (gx + 1.f) * 0.5f * (float)(w - 1);
        float fy = (gy + 1.f) * 0.5f * (float)(w - 1);
        float x0f = floorf(fx), y0f = floorf(fy);
        float wx1 = fx - x0f, wy1 = fy - y0f;
        float wx0 = 1.f - wx1, wy0 = 1.f - wy1;
        int x0 = min(max((int)x0f, 0), w - 1);
        int x1 = min(max((int)x0f + 1, 0), w - 1);
        int y0 = min(max((int)y0f, 0), w - 1);
        int y1 = min(max((int)y0f + 1, 0), w - 1);
        size_t base = POm + (size_t)b * HWm * 128;
        float4 c00 = ((const float4*)&g_P[base + (size_t)(y0 * w + x0) * 128])[lane];
        float4 c01 = ((const float4*)&g_P[base + (size_t)(y0 * w + x1) * 128])[lane];
        float4 c10 = ((const float4*)&g_P[base + (size_t)(y1 * w + x0) * 128])[lane];
        float4 c11 = ((const float4*)&g_P[base + (size_t)(y1 * w + x1) * 128])[lane];
        float w00 = wy0 * wx0, w01 = wy0 * wx1, w10 = wy1 * wx0, w11 = wy1 * wx1;
        acc.x += w00 * c00.x + w01 * c01.x + w10 * c10.x + w11 * c11.x;
        acc.y += w00 * c00.y + w01 * c01.y + w10 * c10.y + w11 * c11.y;
        acc.z += w00 * c00.z + w01 * c01.z + w10 * c10.z + w11 * c11.z;
        acc.w += w00 * c00.w + w01 * c01.w + w10 * c10.w + w11 * c11.w;
    }
    float4 bb = ((const float4*)bias)[lane];
    acc.x = fmaxf(acc.x + bb.x, 0.f);
    acc.y = fmaxf(acc.y + bb.y, 0.f);
    acc.z = fmaxf(acc.z + bb.z, 0.f);
    acc.w = fmaxf(acc.w + bb.w, 0.f);
    float* row = &g_X0[(size_t)v * XSTR];
    ((float4*)row)[lane] = acc;
    if (lane < 3) row[128 + lane] = vp[(size_t)v * 3 + lane];
#pragma unroll
    for (int j = 0; j < 8; j++)
        row[131 + lane * 8 + j] = enc[(size_t)b * 256 + lane * 8 + j];
}

// =========================================================================
// CSR build (edges are INT32)
// =========================================================================
__global__ void hist_kernel(const int* __restrict__ edges, int E)
{
    int i = blockIdx.x * blockDim.x + threadIdx.x;
    if (i >= E) return;
    atomicAdd(&g_cnt[edges[2 * i]], 1);
    atomicAdd(&g_cnt[edges[2 * i + 1]], 1);
}

__global__ void scan_kernel()
{
    __shared__ int part[1024];
    const int n = NV;
    int t = threadIdx.x;
    int chunk = (n + 1023) >> 10;
    int base = t * chunk;
    int sum = 0;
    for (int j = 0; j < chunk; j++) {
        int idx = base + j;
        if (idx < n) sum += g_cnt[idx];
    }
    part[t] = sum;
    __syncthreads();
    for (int off = 1; off < 1024; off <<= 1) {
        int v = 0;
        if (t >= off) v = part[t - off];
        __syncthreads();
        part[t] += v;
        __syncthreads();
    }
    int run = part[t] - sum;
    for (int j = 0; j < chunk; j++) {
        int idx = base + j;
        if (idx < n) { g_offs[idx] = run; run += g_cnt[idx]; }
    }
    if (t == 1023) g_offs[n] = part[1023];
}

__global__ void fill_kernel(const int* __restrict__ edges, int E)
{
    int i = blockIdx.x * blockDim.x + threadIdx.x;
    if (i >= E) return;
    int v0 = edges[2 * i];
    int v1 = edges[2 * i + 1];
    int p0 = atomicAdd(&g_cnt[v0], 1);
    g_entries[g_offs[v0] + p0] = v1;
    int p1 = atomicAdd(&g_cnt[v1], 1);
    g_entries[g_offs[v1] + p1] = v0;
}

// =========================================================================
// fp16x3 dual GEMM via mma.m16n8k16:
//   H0 = act(X)@W0+b0 ; g_H1 = act(X)@W1+b1
// BM=128, BN=256, K chunked by 32. 512 threads = 16 warps (2m x 8n),
// warp tile 64x32.  B fragments prepacked in g_pack (copy-only staging).
// d += ah*bl + al*bh + ah*bh  (lo*lo dropped).
// =========================================================================
__global__ void __launch_bounds__(512, 1) gemm_f16x3(
    int xsel, int Kin, int reluIn, int img0,
    const float* __restrict__ b0, const float* __restrict__ b1,
    int osel)
{
    __shared__ uint32_t sAh[2048], sAl[2048];   // 8KB + 8KB
    __shared__ uint32_t sBh[4096], sBl[4096];   // 16KB + 16KB

    const float* X = (xsel == 0) ? g_X0 : (xsel == 1) ? g_bufA : g_bufB;
    int ldx = (xsel == 0) ? XSTR : 128;
    float* H0 = (osel == 1) ? g_bufA : g_bufB;

    int tid = threadIdx.x;
    int lane = tid & 31;
    int wid = tid >> 5;
    int warp_m = wid >> 3;    // 0..1
    int warp_n = wid & 7;     // 0..7
    int row0 = blockIdx.x * 128;

    float d[4][4][4];
#pragma unroll
    for (int mt = 0; mt < 4; mt++)
#pragma unroll
        for (int nt = 0; nt < 4; nt++)
#pragma unroll
            for (int q = 0; q < 4; q++) d[mt][nt][q] = 0.f;

    int nch = (Kin + 31) >> 5;
    for (int c = 0; c < nch; c++) {
        int kc = c * 32;
        int kmax = min(32, Kin - kc);

        // ---- B copy: prepacked image (hi 4096 w | lo 4096 w) ----
        {
            const uint4* src = (const uint4*)&g_pack[(size_t)(img0 + c) * 8192];
#pragma unroll
            for (int i = 0; i < 4; i++) {
                int idx = tid + i * 512;       // 0..2047 uint4
                uint4 v = src[idx];
                if (idx < 1024) ((uint4*)sBh)[idx] = v;
                else            ((uint4*)sBl)[idx - 1024] = v;
            }
        }
        // ---- A stage: thread owns (row r, 8-k segment cs) ----
        {
            int r  = tid >> 2;
            int cs = tid & 3;
            int grow = row0 + r;
            float vv[8];
            int cbase = cs * 8;
            if (grow < NV && cbase + 8 <= kmax) {
                float4 p0v = *(const float4*)&X[(size_t)grow * ldx + kc + cbase];
                float4 p1v = *(const float4*)&X[(size_t)grow * ldx + kc + cbase + 4];
                vv[0] = p0v.x; vv[1] = p0v.y; vv[2] = p0v.z; vv[3] = p0v.w;
                vv[4] = p1v.x; vv[5] = p1v.y; vv[6] = p1v.z; vv[7] = p1v.w;
            } else {
#pragma unroll
                for (int j = 0; j < 8; j++) {
                    int kk = cbase + j;
                    vv[j] = (grow < NV && kk < kmax)
                          ? X[(size_t)grow * ldx + kc + kk] : 0.f;
                }
            }
            __half hh[8], ll[8];
#pragma unroll
            for (int j = 0; j < 8; j++) {
                float x = vv[j];
                if (reluIn) x = fmaxf(x, 0.f);
                __half hi = __float2half_rn(x);
                hh[j] = hi;
                ll[j] = __float2half_rn(x - __half2float(hi));
            }
            int rr = r & 15;
            int blk = (r >> 4) * 2 + (cs >> 1);
            int rg  = (cs & 1) * 2 + ((rr >= 8) ? 1 : 0);
            int wbase = blk * 128 + (rr & 7) * 16 + rg;
#pragma unroll
            for (int t = 0; t < 4; t++) {
                sAh[wbase + t * 4] = pack_h2(hh[2 * t], hh[2 * t + 1]);
                sAl[wbase + t * 4] = pack_h2(ll[2 * t], ll[2 * t + 1]);
            }
        }
        __syncthreads();

        // ---- compute: 2 k-steps of m16n8k16, 3 passes ----
#pragma unroll
        for (int ks = 0; ks < 2; ks++) {
            uint32_t bh[4][2], bl[4][2];
#pragma unroll
            for (int nt = 0; nt < 4; nt++) {
                int Ni = warp_n * 4 + nt;
                int w = ((Ni * 2 + ks) * 32 + lane) * 2;
                uint2 th = *(const uint2*)&sBh[w];
                uint2 tl = *(const uint2*)&sBl[w];
                bh[nt][0] = th.x; bh[nt][1] = th.y;
                bl[nt][0] = tl.x; bl[nt][1] = tl.y;
            }
#pragma unroll
            for (int mt = 0; mt < 4; mt++) {
                int Mi = warp_m * 4 + mt;
                int w = ((Mi * 2 + ks) * 32 + lane) * 4;
                uint4 th = *(const uint4*)&sAh[w];
                uint4 tl = *(const uint4*)&sAl[w];
                uint32_t ah[4] = {th.x, th.y, th.z, th.w};
                uint32_t al[4] = {tl.x, tl.y, tl.z, tl.w};
#pragma unroll
                for (int nt = 0; nt < 4; nt++) {
                    mma_f16(d[mt][nt], ah, bl[nt]);
                    mma_f16(d[mt][nt], al, bh[nt]);
                    mma_f16(d[mt][nt], ah, bh[nt]);
                }
            }
        }
        __syncthreads();
    }
    // ---- epilogue ----
#pragma unroll
    for (int nt = 0; nt < 4; nt++) {
        int gcol = warp_n * 32 + nt * 8;
        float* Hout; const float* bias; int cb;
        if (gcol < 128) { Hout = H0;   bias = b0; cb = gcol; }
        else            { Hout = g_H1; bias = b1; cb = gcol - 128; }
        int c0 = cb + (lane & 3) * 2;
        float2 bv = *(const float2*)&bias[c0];
#pragma unroll
        for (int mt = 0; mt < 4; mt++) {
            int rtop = row0 + warp_m * 64 + mt * 16 + (lane >> 2);
            if (rtop < NV) {
                float2 o = make_float2(d[mt][nt][0] + bv.x, d[mt][nt][1] + bv.y);
                *(float2*)&Hout[(size_t)rtop * 128 + c0] = o;
            }
            int rbot = rtop + 8;
            if (rbot < NV) {
                float2 o = make_float2(d[mt][nt][2] + bv.x, d[mt][nt][3] + bv.y);
                *(float2*)&Hout[(size_t)rbot * 128 + c0] = o;
            }
        }
    }
}

// =========================================================================
// Gather: OUT[v] (holding h0) += sum_{nb in adj(v)} g_H1[nb]
// =========================================================================
__global__ void gather_kernel(int osel)
{
    float* OUT = (osel == 1) ? g_bufA : g_bufB;
    int gwarp = (blockIdx.x * blockDim.x + threadIdx.x) >> 5;
    int lane = threadIdx.x & 31;
    if (gwarp >= NV) return;
    int v = gwarp;
    int s = g_offs[v], e = g_offs[v + 1];
    float4 acc = ((const float4*)&OUT[(size_t)v * 128])[lane];
    for (int i = s; i < e; i++) {
        int nb = g_entries[i];
        float4 h = ((const float4*)&g_H1[(size_t)nb * 128])[lane];
        acc.x += h.x; acc.y += h.y; acc.z += h.z; acc.w += h.w;
    }
    ((float4*)&OUT[(size_t)v * 128])[lane] = acc;
}

// =========================================================================
// Final projection: out = relu(X) @ off_w + off_b   (128 -> 3)
// =========================================================================
__global__ void final_kernel(int xsel,
                             const float* __restrict__ ow, const float* __restrict__ ob,
                             float* __restrict__ out)
{
    const float* X = (xsel == 1) ? g_bufA : g_bufB;
    int gwarp = (blockIdx.x * blockDim.x + threadIdx.x) >> 5;
    int lane = threadIdx.x & 31;
    if (gwarp >= NV) return;
    int v = gwarp;
    float4 x = ((const float4*)&X[(size_t)v * 128])[lane];
    x.x = fmaxf(x.x, 0.f); x.y = fmaxf(x.y, 0.f);
    x.z = fmaxf(x.z, 0.f); x.w = fmaxf(x.w, 0.f);
    const float* wr = &ow[(size_t)(lane * 4) * 3];
    float s0 = x.x * wr[0] + x.y * wr[3] + x.z * wr[6] + x.w * wr[9];
    float s1 = x.x * wr[1] + x.y * wr[4] + x.z * wr[7] + x.w * wr[10];
    float s2 = x.x * wr[2] + x.y * wr[5] + x.z * wr[8] + x.w * wr[11];
#pragma unroll
    for (int o = 16; o > 0; o >>= 1) {
        s0 += __shfl_down_sync(0xffffffffu, s0, o);
        s1 += __shfl_down_sync(0xffffffffu, s1, o);
        s2 += __shfl_down_sync(0xffffffffu, s2, o);
    }
    if (lane == 0) {
        out[(size_t)v * 3 + 0] = s0 + ob[0];
        out[(size_t)v * 3 + 1] = s1 + ob[1];
        out[(size_t)v * 3 + 2] = s2 + ob[2];
    }
}

// =========================================================================
extern "C" void kernel_launch(void* const* d_in, const int* in_sizes, int n_in,
                              void* d_out, int out_size)
{
    const float* f1   = (const float*)d_in[0];
    const float* f2   = (const float*)d_in[1];
    const float* f3   = (const float*)d_in[2];
    const float* f4   = (const float*)d_in[3];
    const float* av   = (const float*)d_in[4];
    const float* vp   = (const float*)d_in[5];
    const float* enc  = (const float*)d_in[6];
    const int*   edges = (const int*)d_in[7];
    const float* bw   = (const float*)d_in[8];
    const float* bb   = (const float*)d_in[9];
    const float* g0w0 = (const float*)d_in[10];
    const float* g0b0 = (const float*)d_in[11];
    const float* g0w1 = (const float*)d_in[12];
    const float* g0b1 = (const float*)d_in[13];
    const float* gw0  = (const float*)d_in[14];
    const float* gb0  = (const float*)d_in[15];
    const float* gw1  = (const float*)d_in[16];
    const float* gb1  = (const float*)d_in[17];
    const float* ow   = (const float*)d_in[18];
    const float* ob   = (const float*)d_in[19];
    float* out = (float*)d_out;

    int E = in_sizes[7] / 2;

    const int WARP_GRID = (NV + 7) / 8;
    const int GEMM_GRID = (NV + 127) / 128;   // 321

    // weight prepack (one pass; independent of activations)
    prepack_weights<<<(NIMG * 4096 + 255) / 256, 256>>>(g0w0, g0w1, gw0, gw1);

    // P projection tables (split-K -> zero first)
    zero_P_kernel<<<(PTOT / 4 + 255) / 256, 256>>>();
    precompute_kernel<<<396, 128>>>(f1, f2, f3, f4, bw);
    sampler_kernel<<<WARP_GRID, 256>>>(av, vp, enc, bb);

    // CSR build
    zero_cnt_kernel<<<(NV + 255) / 256, 256>>>();
    hist_kernel<<<(E + 255) / 256, 256>>>(edges, E);
    scan_kernel<<<1, 1024>>>();
    zero_cnt_kernel<<<(NV + 255) / 256, 256>>>();
    fill_kernel<<<(E + 255) / 256, 256>>>(edges, E);

    // layer 0 (Kin=387, no relu on input): images 0..12; H0 -> bufA
    gemm_f16x3<<<GEMM_GRID, 512>>>(0, 387, 0, 0, g0b0, g0b1, 1);
    gather_kernel<<<WARP_GRID, 256>>>(1);

    // layers 1..7 (Kin=128, relu on input), ping-pong bufA <-> bufB
    int cur = 1, nxt = 2;
    for (int i = 0; i < 7; i++) {
        int img0 = 13 + i * 4;
        gemm_f16x3<<<GEMM_GRID, 512>>>(cur, 128, 1, img0,
                                       gb0 + (size_t)i * 128,
                                       gb1 + (size_t)i * 128,
                                       nxt);
        gather_kernel<<<WARP_GRID, 256>>>(nxt);
        int t = cur; cur = nxt; nxt = t;
    }

    final_kernel<<<WARP_GRID, 256>>>(cur, ow, ob, out);
}

// round 10
// speedup vs baseline: 1.7697x; 1.0135x over previous
#include <cuda_runtime.h>
#include <cuda_bf16.h>
#include <cuda_fp16.h>
#include <cstdint>

#define NV   40968           // total vertices (B*V)
#define VPER 10242
#define XSTR 392             // padded row stride of X0 (387 used)
#define PTOT 2132480         // total floats in P tables

// P table offsets (floats) per feature map: B*HW*128 cumulative
#define POFF0 0
#define POFF1 1605632
#define POFF2 2007040
#define POFF3 2107392

// weight images: 41 images (layer0: 13 chunks, layers1-7: 4 each), each
// 8192 uint32 words (hi 4096 | lo 4096) in mma fragment layout.
#define NIMG 41

// ---------------- device scratch (module globals; no allocations) --------
__device__ float g_P[PTOT];
__device__ float g_X0[(size_t)NV * XSTR];
__device__ float g_bufA[(size_t)NV * 128];
__device__ float g_bufB[(size_t)NV * 128];
__device__ float g_H1[(size_t)NV * 128];
__device__ int   g_cnt[NV];
__device__ int   g_offs[NV + 1];
__device__ int   g_entries[245760];
__device__ __align__(16) uint32_t g_pack[NIMG * 8192];

// ---------------- f32x2 helpers (precompute kernel) ----------------
__device__ __forceinline__ unsigned long long dup2(float x) {
    unsigned long long r;
    asm("mov.b64 %0, {%1, %1};" : "=l"(r) : "f"(x));
    return r;
}
__device__ __forceinline__ void ffma2(unsigned long long &d, unsigned long long a, unsigned long long b) {
    asm("fma.rn.f32x2 %0, %1, %2, %0;" : "+l"(d) : "l"(a), "l"(b));
}
__device__ __forceinline__ float2 unpk(unsigned long long v) {
    float2 r;
    asm("mov.b64 {%0, %1}, %2;" : "=f"(r.x), "=f"(r.y) : "l"(v));
    return r;
}

// fp16 mma m16n8k16, f32 accumulate
__device__ __forceinline__ void mma_f16(float* d, const uint32_t* a, const uint32_t* b) {
    asm("mma.sync.aligned.m16n8k16.row.col.f32.f16.f16.f32 "
        "{%0,%1,%2,%3},{%4,%5,%6,%7},{%8,%9},{%0,%1,%2,%3};"
        : "+f"(d[0]), "+f"(d[1]), "+f"(d[2]), "+f"(d[3])
        : "r"(a[0]), "r"(a[1]), "r"(a[2]), "r"(a[3]), "r"(b[0]), "r"(b[1]));
}
__device__ __forceinline__ uint32_t pack_h2(__half a, __half b) {
    __half2 h2 = __halves2half2(a, b);
    return *(uint32_t*)&h2;
}

// =========================================================================
// zero kernels
// =========================================================================
__global__ void zero_cnt_kernel()
{
    int i = blockIdx.x * blockDim.x + threadIdx.x;
    if (i < NV) g_cnt[i] = 0;
}
__global__ void zero_P_kernel()
{
    int i = blockIdx.x * blockDim.x + threadIdx.x;
    if (i < PTOT / 4) ((float4*)g_P)[i] = make_float4(0.f, 0.f, 0.f, 0.f);
}

// =========================================================================
// Weight prepack -> fragment-layout hi/lo fp16 images.
// =========================================================================
__global__ void prepack_weights(
    const float* __restrict__ g0w0, const float* __restrict__ g0w1,
    const float* __restrict__ gw0,  const float* __restrict__ gw1)
{
    int idx = blockIdx.x * 256 + threadIdx.x;
    if (idx >= NIMG * 4096) return;
    int img = idx >> 12;
    int e   = idx & 4095;
    int n   = e >> 4;          // 0..255
    int kp  = e & 15;          // k-pair 0..15 (k = 2*kp)

    const float *W0, *W1; int Kin, chunk;
    if (img < 13) { W0 = g0w0; W1 = g0w1; Kin = 387; chunk = img; }
    else {
        int t = img - 13;
        int L = t >> 2; chunk = t & 3;
        W0 = gw0 + (size_t)L * 16384;
        W1 = gw1 + (size_t)L * 16384;
        Kin = 128;
    }
    const float* W = (n < 128) ? W0 : W1;
    int col = n & 127;
    int kg = chunk * 32 + kp * 2;
    float w0v = (kg     < Kin) ? W[(size_t)kg * 128 + col]       : 0.f;
    float w1v = (kg + 1 < Kin) ? W[(size_t)(kg + 1) * 128 + col] : 0.f;

    __half h0 = __float2half_rn(w0v);
    __half l0 = __float2half_rn(w0v - __half2float(h0));
    __half h1 = __float2half_rn(w1v);
    __half l1 = __float2half_rn(w1v - __half2float(h1));

    int Ni = n >> 3, nn = n & 7;
    int kk = kp * 2;
    int Ks = kk >> 4;
    int kk16 = kk & 15;
    int rg = (kk16 >= 8) ? 1 : 0;
    int t  = (kk16 & 7) >> 1;
    int word = ((Ni * 2 + Ks) * 32 + nn * 4 + t) * 2 + rg;
    size_t base = (size_t)img * 8192;
    g_pack[base + word]        = pack_h2(h0, h1);
    g_pack[base + 4096 + word] = pack_h2(l0, l1);
}

// =========================================================================
// Kernel 1: per-pixel projection, split-K balanced, atomicAdd epilogue.
// =========================================================================
__global__ void __launch_bounds__(128) precompute_kernel(
    const float* __restrict__ f1, const float* __restrict__ f2,
    const float* __restrict__ f3, const float* __restrict__ f4,
    const float* __restrict__ BW)
{
    __shared__ float As[32][68];
    __shared__ float Bs[32][128];

    int bid = blockIdx.x;
    int m, local;
    if (bid < 196)      { m = 0; local = bid; }
    else if (bid < 300) { m = 1; local = bid - 196; }
    else if (bid < 364) { m = 2; local = bid - 300; }
    else                { m = 3; local = bid - 364; }

    const float* fm;
    int HW, C, WO, ks; size_t poff;
    if (m == 0)      { fm = f1; HW = 3136; C = 256;  WO = 0;    poff = POFF0; ks = 1; }
    else if (m == 1) { fm = f2; HW = 784;  C = 512;  WO = 256;  poff = POFF1; ks = 2; }
    else if (m == 2) { fm = f3; HW = 196;  C = 1024; WO = 768;  poff = POFF2; ks = 4; }
    else             { fm = f4; HW = 49;   C = 2048; WO = 1792; poff = POFF3; ks = 8; }

    int kt   = local % ks;
    int rest = local / ks;
    int b  = rest & 3;
    int mt = rest >> 2;

    int p0  = mt * 64;
    int kc0 = kt * 256;
    int tid = threadIdx.x;
    int rowg = tid & 7;
    int colg = tid >> 3;
    int r0 = rowg * 8;
    int c0 = colg * 8;

    unsigned long long acc[8][4];
#pragma unroll
    for (int i = 0; i < 8; i++)
#pragma unroll
        for (int j = 0; j < 4; j++) acc[i][j] = 0ULL;

    for (int ch = 0; ch < 8; ch++) {
        int kk = kc0 + ch * 32;
#pragma unroll
        for (int i = 0; i < 16; i++) {
            int lin = tid + i * 128;
            int c = lin >> 6;
            int p = lin & 63;
            float v = 0.f;
            if (p0 + p < HW)
                v = fm[((size_t)b * C + (kk + c)) * HW + p0 + p];
            As[c][p] = v;
        }
#pragma unroll
        for (int i = 0; i < 8; i++) {
            int lin4 = tid + i * 128;
            int k = lin4 >> 5;
            int n4 = (lin4 & 31) * 4;
            float4 v = *(const float4*)&BW[(size_t)(WO + kk + k) * 128 + n4];
            *(float4*)&Bs[k][n4] = v;
        }
        __syncthreads();
#pragma unroll 2
        for (int k = 0; k < 32; k++) {
            float4 aA = *(const float4*)&As[k][r0];
            float4 aB = *(const float4*)&As[k][r0 + 4];
            unsigned long long ad[8] = {dup2(aA.x), dup2(aA.y), dup2(aA.z), dup2(aA.w),
                                        dup2(aB.x), dup2(aB.y), dup2(aB.z), dup2(aB.w)};
            ulonglong2 bp0 = *(const ulonglong2*)&Bs[k][c0];
            ulonglong2 bp1 = *(const ulonglong2*)&Bs[k][c0 + 4];
            unsigned long long bb[4] = {bp0.x, bp0.y, bp1.x, bp1.y};
#pragma unroll
            for (int i = 0; i < 8; i++)
#pragma unroll
                for (int j = 0; j < 4; j++) ffma2(acc[i][j], ad[i], bb[j]);
        }
        __syncthreads();
    }
    size_t pbase = poff + (size_t)b * HW * 128;
#pragma unroll
    for (int i = 0; i < 8; i++) {
        int pix = p0 + r0 + i;
        if (pix >= HW) continue;
        float* dst = &g_P[pbase + (size_t)pix * 128 + c0];
        if (ks == 1) {
#pragma unroll
            for (int j = 0; j < 2; j++) {
                float2 vA = unpk(acc[i][j * 2]);
                float2 vB = unpk(acc[i][j * 2 + 1]);
                *(float4*)&dst[j * 4] = make_float4(vA.x, vA.y, vB.x, vB.y);
            }
        } else {
#pragma unroll
            for (int j = 0; j < 4; j++) {
                float2 v = unpk(acc[i][j]);
                atomicAdd(&dst[j * 2 + 0], v.x);
                atomicAdd(&dst[j * 2 + 1], v.y);
            }
        }
    }
}

// =========================================================================
// Kernel 2: bilinear sampler + bias + relu + assemble X0 row
// =========================================================================
__global__ void sampler_kernel(
    const float* __restrict__ av, const float* __restrict__ vp,
    const float* __restrict__ enc, const float* __restrict__ bias)
{
    int gwarp = (blockIdx.x * blockDim.x + threadIdx.x) >> 5;
    int lane = threadIdx.x & 31;
    if (gwarp >= NV) return;
    int v = gwarp;
    int b = v / VPER;

    float gx = av[(size_t)v * 3 + 0];
    float gy = av[(size_t)v * 3 + 1];

    float4 acc = make_float4(0.f, 0.f, 0.f, 0.f);
#pragma unroll
    for (int m = 0; m < 4; m++) {
        const int DIMm = (m == 0) ? 56 : (m == 1) ? 28 : (m == 2) ? 14 : 7;
        const int HWm  = DIMm * DIMm;
        const size_t POm = (m == 0) ? POFF0 : (m == 1) ? POFF1 : (m == 2) ? POFF2 : POFF3;
        int w = DIMm;
        float fx = (gx + 1.f) * 0.5f * (float)(w - 1);
        float fy = (gy + 1.f) * 0.5f * (float)(w - 1);
        float x0f = floorf(fx), y0f = floorf(fy);
        float wx1 = fx - x0f, wy1 = fy - y0f;
        float wx0 = 1.f - wx1, wy0 = 1.f - wy1;
        int x0 = min(max((int)x0f, 0), w - 1);
        int x1 = min(max((int)x0f + 1, 0), w - 1);
        int y0 = min(max((int)y0f, 0), w - 1);
        int y1 = min(max((int)y0f + 1, 0), w - 1);
        size_t base = POm + (size_t)b * HWm * 128;
        float4 c00 = ((const float4*)&g_P[base + (size_t)(y0 * w + x0) * 128])[lane];
        float4 c01 = ((const float4*)&g_P[base + (size_t)(y0 * w + x1) * 128])[lane];
        float4 c10 = ((const float4*)&g_P[base + (size_t)(y1 * w + x0) * 128])[lane];
        float4 c11 = ((const float4*)&g_P[base + (size_t)(y1 * w + x1) * 128])[lane];
        float w00 = wy0 * wx0, w01 = wy0 * wx1, w10 = wy1 * wx0, w11 = wy1 * wx1;
        acc.x += w00 * c00.x + w01 * c01.x + w10 * c10.x + w11 * c11.x;
        acc.y += w00 * c00.y + w01 * c01.y + w10 * c10.y + w11 * c11.y;
        acc.z += w00 * c00.z + w01 * c01.z + w10 * c10.z + w11 * c11.z;
        acc.w += w00 * c00.w + w01 * c01.w + w10 * c10.w + w11 * c11.w;
    }
    float4 bb = ((const float4*)bias)[lane];
    acc.x = fmaxf(acc.x + bb.x, 0.f);
    acc.y = fmaxf(acc.y + bb.y, 0.f);
    acc.z = fmaxf(acc.z + bb.z, 0.f);
    acc.w = fmaxf(acc.w + bb.w, 0.f);
    float* row = &g_X0[(size_t)v * XSTR];
    ((float4*)row)[lane] = acc;
    if (lane < 3) row[128 + lane] = vp[(size_t)v * 3 + lane];
#pragma unroll
    for (int j = 0; j < 8; j++)
        row[131 + lane * 8 + j] = enc[(size_t)b * 256 + lane * 8 + j];
}

// =========================================================================
// CSR build (edges are INT32)
// =========================================================================
__global__ void hist_kernel(const int* __restrict__ edges, int E)
{
    int i = blockIdx.x * blockDim.x + threadIdx.x;
    if (i >= E) return;
    atomicAdd(&g_cnt[edges[2 * i]], 1);
    atomicAdd(&g_cnt[edges[2 * i + 1]], 1);
}

__global__ void scan_kernel()
{
    __shared__ int part[1024];
    const int n = NV;
    int t = threadIdx.x;
    int chunk = (n + 1023) >> 10;
    int base = t * chunk;
    int sum = 0;
    for (int j = 0; j < chunk; j++) {
        int idx = base + j;
        if (idx < n) sum += g_cnt[idx];
    }
    part[t] = sum;
    __syncthreads();
    for (int off = 1; off < 1024; off <<= 1) {
        int v = 0;
        if (t >= off) v = part[t - off];
        __syncthreads();
        part[t] += v;
        __syncthreads();
    }
    int run = part[t] - sum;
    for (int j = 0; j < chunk; j++) {
        int idx = base + j;
        if (idx < n) { g_offs[idx] = run; run += g_cnt[idx]; }
    }
    if (t == 1023) g_offs[n] = part[1023];
}

__global__ void fill_kernel(const int* __restrict__ edges, int E)
{
    int i = blockIdx.x * blockDim.x + threadIdx.x;
    if (i >= E) return;
    int v0 = edges[2 * i];
    int v1 = edges[2 * i + 1];
    int p0 = atomicAdd(&g_cnt[v0], 1);
    g_entries[g_offs[v0] + p0] = v1;
    int p1 = atomicAdd(&g_cnt[v1], 1);
    g_entries[g_offs[v1] + p1] = v0;
}

// =========================================================================
// fp16x3 dual GEMM via mma.m16n8k16, DOUBLE-BUFFERED staging:
//   H0 = act(X)@W0+b0 ; g_H1 = act(X)@W1+b1
// BM=128, BN=256, K chunked by 32. 512 threads = 16 warps (2m x 8n),
// warp tile 64x32. While computing chunk c, warps stage chunk c+1 into
// the other smem buffer; one __syncthreads per iteration.
// Buffer layout (uint32 words): Ah[2048] Al[2048] Bh[4096] Bl[4096]
// =========================================================================
#define BUFW 12288                    // words per buffer
#define SMEM_GEMM_BYTES (2 * BUFW * 4)   // 96 KB

__global__ void __launch_bounds__(512, 1) gemm_f16x3(
    int xsel, int Kin, int reluIn, int img0,
    const float* __restrict__ b0, const float* __restrict__ b1,
    int osel)
{
    extern __shared__ uint32_t smw[];

    const float* X = (xsel == 0) ? g_X0 : (xsel == 1) ? g_bufA : g_bufB;
    int ldx = (xsel == 0) ? XSTR : 128;
    float* H0 = (osel == 1) ? g_bufA : g_bufB;

    int tid = threadIdx.x;
    int lane = tid & 31;
    int wid = tid >> 5;
    int warp_m = wid >> 3;    // 0..1
    int warp_n = wid & 7;     // 0..7
    int row0 = blockIdx.x * 128;

    float d[4][4][4];
#pragma unroll
    for (int mt = 0; mt < 4; mt++)
#pragma unroll
        for (int nt = 0; nt < 4; nt++)
#pragma unroll
            for (int q = 0; q < 4; q++) d[mt][nt][q] = 0.f;

    int nch = (Kin + 31) >> 5;

    // staging lambda: chunk c -> buffer buf (0/1)
    auto stage = [&](int c, int buf) {
        uint32_t* sAh = smw + buf * BUFW;
        uint32_t* sAl = sAh + 2048;
        uint32_t* sBh = sAh + 4096;
        uint32_t* sBl = sAh + 8192;
        int kc = c * 32;
        int kmax = min(32, Kin - kc);
        // B copy (prepacked fragments)
        const uint4* src = (const uint4*)&g_pack[(size_t)(img0 + c) * 8192];
#pragma unroll
        for (int i = 0; i < 4; i++) {
            int idx = tid + i * 512;       // 0..2047 uint4
            uint4 v = src[idx];
            if (idx < 1024) ((uint4*)sBh)[idx] = v;
            else            ((uint4*)sBl)[idx - 1024] = v;
        }
        // A stage: thread owns (row r, 8-k segment cs)
        int r  = tid >> 2;
        int cs = tid & 3;
        int grow = row0 + r;
        float vv[8];
        int cbase = cs * 8;
        if (grow < NV && cbase + 8 <= kmax) {
            float4 p0v = *(const float4*)&X[(size_t)grow * ldx + kc + cbase];
            float4 p1v = *(const float4*)&X[(size_t)grow * ldx + kc + cbase + 4];
            vv[0] = p0v.x; vv[1] = p0v.y; vv[2] = p0v.z; vv[3] = p0v.w;
            vv[4] = p1v.x; vv[5] = p1v.y; vv[6] = p1v.z; vv[7] = p1v.w;
        } else {
#pragma unroll
            for (int j = 0; j < 8; j++) {
                int kk = cbase + j;
                vv[j] = (grow < NV && kk < kmax)
                      ? X[(size_t)grow * ldx + kc + kk] : 0.f;
            }
        }
        __half hh[8], ll[8];
#pragma unroll
        for (int j = 0; j < 8; j++) {
            float x = vv[j];
            if (reluIn) x = fmaxf(x, 0.f);
            __half hi = __float2half_rn(x);
            hh[j] = hi;
            ll[j] = __float2half_rn(x - __half2float(hi));
        }
        int rr = r & 15;
        int blk = (r >> 4) * 2 + (cs >> 1);
        int rg  = (cs & 1) * 2 + ((rr >= 8) ? 1 : 0);
        int wbase = blk * 128 + (rr & 7) * 16 + rg;
#pragma unroll
        for (int t = 0; t < 4; t++) {
            sAh[wbase + t * 4] = pack_h2(hh[2 * t], hh[2 * t + 1]);
            sAl[wbase + t * 4] = pack_h2(ll[2 * t], ll[2 * t + 1]);
        }
    };

    stage(0, 0);
    __syncthreads();

    for (int c = 0; c < nch; c++) {
        int buf = c & 1;
        if (c + 1 < nch) stage(c + 1, buf ^ 1);

        uint32_t* sAh = smw + buf * BUFW;
        uint32_t* sAl = sAh + 2048;
        uint32_t* sBh = sAh + 4096;
        uint32_t* sBl = sAh + 8192;
#pragma unroll
        for (int ks = 0; ks < 2; ks++) {
            uint32_t bh[4][2], bl[4][2];
#pragma unroll
            for (int nt = 0; nt < 4; nt++) {
                int Ni = warp_n * 4 + nt;
                int w = ((Ni * 2 + ks) * 32 + lane) * 2;
                uint2 th = *(const uint2*)&sBh[w];
                uint2 tl = *(const uint2*)&sBl[w];
                bh[nt][0] = th.x; bh[nt][1] = th.y;
                bl[nt][0] = tl.x; bl[nt][1] = tl.y;
            }
#pragma unroll
            for (int mt = 0; mt < 4; mt++) {
                int Mi = warp_m * 4 + mt;
                int w = ((Mi * 2 + ks) * 32 + lane) * 4;
                uint4 th = *(const uint4*)&sAh[w];
                uint4 tl = *(const uint4*)&sAl[w];
                uint32_t ah[4] = {th.x, th.y, th.z, th.w};
                uint32_t al[4] = {tl.x, tl.y, tl.z, tl.w};
#pragma unroll
                for (int nt = 0; nt < 4; nt++) {
                    mma_f16(d[mt][nt], ah, bl[nt]);
                    mma_f16(d[mt][nt], al, bh[nt]);
                    mma_f16(d[mt][nt], ah, bh[nt]);
                }
            }
        }
        __syncthreads();
    }
    // ---- epilogue ----
#pragma unroll
    for (int nt = 0; nt < 4; nt++) {
        int gcol = warp_n * 32 + nt * 8;
        float* Hout; const float* bias; int cb;
        if (gcol < 128) { Hout = H0;   bias = b0; cb = gcol; }
        else            { Hout = g_H1; bias = b1; cb = gcol - 128; }
        int c0 = cb + (lane & 3) * 2;
        float2 bv = *(const float2*)&bias[c0];
#pragma unroll
        for (int mt = 0; mt < 4; mt++) {
            int rtop = row0 + warp_m * 64 + mt * 16 + (lane >> 2);
            if (rtop < NV) {
                float2 o = make_float2(d[mt][nt][0] + bv.x, d[mt][nt][1] + bv.y);
                *(float2*)&Hout[(size_t)rtop * 128 + c0] = o;
            }
            int rbot = rtop + 8;
            if (rbot < NV) {
                float2 o = make_float2(d[mt][nt][2] + bv.x, d[mt][nt][3] + bv.y);
                *(float2*)&Hout[(size_t)rbot * 128 + c0] = o;
            }
        }
    }
}

// =========================================================================
// Gather: OUT[v] (holding h0) += sum_{nb in adj(v)} g_H1[nb]
// =========================================================================
__global__ void gather_kernel(int osel)
{
    float* OUT = (osel == 1) ? g_bufA : g_bufB;
    int gwarp = (blockIdx.x * blockDim.x + threadIdx.x) >> 5;
    int lane = threadIdx.x & 31;
    if (gwarp >= NV) return;
    int v = gwarp;
    int s = g_offs[v], e = g_offs[v + 1];
    float4 acc = ((const float4*)&OUT[(size_t)v * 128])[lane];
    for (int i = s; i < e; i++) {
        int nb = g_entries[i];
        float4 h = ((const float4*)&g_H1[(size_t)nb * 128])[lane];
        acc.x += h.x; acc.y += h.y; acc.z += h.z; acc.w += h.w;
    }
    ((float4*)&OUT[(size_t)v * 128])[lane] = acc;
}

// =========================================================================
// Final projection: out = relu(X) @ off_w + off_b   (128 -> 3)
// =========================================================================
__global__ void final_kernel(int xsel,
                             const float* __restrict__ ow, const float* __restrict__ ob,
                             float* __restrict__ out)
{
    const float* X = (xsel == 1) ? g_bufA : g_bufB;
    int gwarp = (blockIdx.x * blockDim.x + threadIdx.x) >> 5;
    int lane = threadIdx.x & 31;
    if (gwarp >= NV) return;
    int v = gwarp;
    float4 x = ((const float4*)&X[(size_t)v * 128])[lane];
    x.x = fmaxf(x.x, 0.f); x.y = fmaxf(x.y, 0.f);
    x.z = fmaxf(x.z, 0.f); x.w = fmaxf(x.w, 0.f);
    const float* wr = &ow[(size_t)(lane * 4) * 3];
    float s0 = x.x * wr[0] + x.y * wr[3] + x.z * wr[6] + x.w * wr[9];
    float s1 = x.x * wr[1] + x.y * wr[4] + x.z * wr[7] + x.w * wr[10];
    float s2 = x.x * wr[2] + x.y * wr[5] + x.z * wr[8] + x.w * wr[11];
#pragma unroll
    for (int o = 16; o > 0; o >>= 1) {
        s0 += __shfl_down_sync(0xffffffffu, s0, o);
        s1 += __shfl_down_sync(0xffffffffu, s1, o);
        s2 += __shfl_down_sync(0xffffffffu, s2, o);
    }
    if (lane == 0) {
        out[(size_t)v * 3 + 0] = s0 + ob[0];
        out[(size_t)v * 3 + 1] = s1 + ob[1];
        out[(size_t)v * 3 + 2] = s2 + ob[2];
    }
}

// =========================================================================
extern "C" void kernel_launch(void* const* d_in, const int* in_sizes, int n_in,
                              void* d_out, int out_size)
{
    const float* f1   = (const float*)d_in[0];
    const float* f2   = (const float*)d_in[1];
    const float* f3   = (const float*)d_in[2];
    const float* f4   = (const float*)d_in[3];
    const float* av   = (const float*)d_in[4];
    const float* vp   = (const float*)d_in[5];
    const float* enc  = (const float*)d_in[6];
    const int*   edges = (const int*)d_in[7];
    const float* bw   = (const float*)d_in[8];
    const float* bb   = (const float*)d_in[9];
    const float* g0w0 = (const float*)d_in[10];
    const float* g0b0 = (const float*)d_in[11];
    const float* g0w1 = (const float*)d_in[12];
    const float* g0b1 = (const float*)d_in[13];
    const float* gw0  = (const float*)d_in[14];
    const float* gb0  = (const float*)d_in[15];
    const float* gw1  = (const float*)d_in[16];
    const float* gb1  = (const float*)d_in[17];
    const float* ow   = (const float*)d_in[18];
    const float* ob   = (const float*)d_in[19];
    float* out = (float*)d_out;

    int E = in_sizes[7] / 2;

    cudaFuncSetAttribute(gemm_f16x3,
                         cudaFuncAttributeMaxDynamicSharedMemorySize,
                         SMEM_GEMM_BYTES);

    const int WARP_GRID = (NV + 7) / 8;
    const int GEMM_GRID = (NV + 127) / 128;   // 321

    // weight prepack (one pass; independent of activations)
    prepack_weights<<<(NIMG * 4096 + 255) / 256, 256>>>(g0w0, g0w1, gw0, gw1);

    // P projection tables (split-K -> zero first)
    zero_P_kernel<<<(PTOT / 4 + 255) / 256, 256>>>();
    precompute_kernel<<<396, 128>>>(f1, f2, f3, f4, bw);
    sampler_kernel<<<WARP_GRID, 256>>>(av, vp, enc, bb);

    // CSR build
    zero_cnt_kernel<<<(NV + 255) / 256, 256>>>();
    hist_kernel<<<(E + 255) / 256, 256>>>(edges, E);
    scan_kernel<<<1, 1024>>>();
    zero_cnt_kernel<<<(NV + 255) / 256, 256>>>();
    fill_kernel<<<(E + 255) / 256, 256>>>(edges, E);

    // layer 0 (Kin=387, no relu on input): images 0..12; H0 -> bufA
    gemm_f16x3<<<GEMM_GRID, 512, SMEM_GEMM_BYTES>>>(0, 387, 0, 0, g0b0, g0b1, 1);
    gather_kernel<<<WARP_GRID, 256>>>(1);

    // layers 1..7 (Kin=128, relu on input), ping-pong bufA <-> bufB
    int cur = 1, nxt = 2;
    for (int i = 0; i < 7; i++) {
        int img0 = 13 + i * 4;
        gemm_f16x3<<<GEMM_GRID, 512, SMEM_GEMM_BYTES>>>(cur, 128, 1, img0,
                                       gb0 + (size_t)i * 128,
                                       gb1 + (size_t)i * 128,
                                       nxt);
        gather_kernel<<<WARP_GRID, 256>>>(nxt);
        int t = cur; cur = nxt; nxt = t;
    }

    final_kernel<<<WARP_GRID, 256>>>(cur, ow, ob, out);
}